// round 9
// baseline (speedup 1.0000x reference)
#include <cuda_runtime.h>
#include <cuda_bf16.h>
#include <cstdint>

#define NN      20000
#define EE      320000
#define IN_DIM  256
#define H0      4
#define D0      128
#define F1      512     // H0*D0
#define OUTF    64

// ---------------- device scratch (allocation-free contract) ----------------
__device__ float g_feat1[(size_t)NN * F1];
__device__ float g_feat2[(size_t)NN * OUTF];
__device__ __nv_bfloat16 g_xhi[(size_t)NN * IN_DIM];
__device__ __nv_bfloat16 g_xlo[(size_t)NN * IN_DIM];
__device__ __nv_bfloat16 g_hhi[(size_t)NN * F1];
__device__ __nv_bfloat16 g_hlo[(size_t)NN * F1];
__device__ __nv_bfloat16 g_w1t_hi[(size_t)F1 * IN_DIM];
__device__ __nv_bfloat16 g_w1t_lo[(size_t)F1 * IN_DIM];
__device__ __nv_bfloat16 g_w2t_hi[(size_t)OUTF * F1];
__device__ __nv_bfloat16 g_w2t_lo[(size_t)OUTF * F1];
__device__ float g_el1[NN * H0];
__device__ float g_er1[NN * H0];
__device__ float g_el2[NN];
__device__ float g_er2[NN];
__device__ int   g_deg[NN];
__device__ int   g_rowptr[NN + 1];
__device__ int   g_csr_src[EE];

// ---------------- helpers ----------------
__device__ __forceinline__ uint32_t smem_u32(const void* p) {
    uint32_t a;
    asm("{ .reg .u64 t; cvta.to.shared.u64 t, %1; cvt.u32.u64 %0, t; }" : "=r"(a) : "l"(p));
    return a;
}
__device__ __forceinline__ void ldsm_x4(uint32_t* r, uint32_t addr) {
    asm volatile("ldmatrix.sync.aligned.m8n8.x4.shared.b16 {%0,%1,%2,%3}, [%4];"
                 : "=r"(r[0]), "=r"(r[1]), "=r"(r[2]), "=r"(r[3]) : "r"(addr));
}
__device__ __forceinline__ void mma_bf16(float* c, const uint32_t* a, const uint32_t* b) {
    asm volatile(
        "mma.sync.aligned.m16n8k16.row.col.f32.bf16.bf16.f32 "
        "{%0,%1,%2,%3}, {%4,%5,%6,%7}, {%8,%9}, {%0,%1,%2,%3};"
        : "+f"(c[0]), "+f"(c[1]), "+f"(c[2]), "+f"(c[3])
        : "r"(a[0]), "r"(a[1]), "r"(a[2]), "r"(a[3]), "r"(b[0]), "r"(b[1]));
}
__device__ __forceinline__ uint32_t swz(int off) { return off ^ ((off >> 3) & 0x70); }
__device__ __forceinline__ float leaky(float e) { return fmaxf(e, 0.2f * e); }

// ---------------- CSR build ----------------
__global__ void zero_deg_kernel() {
    int i = blockIdx.x * blockDim.x + threadIdx.x;
    if (i < NN) g_deg[i] = 0;
}
__global__ void count_deg_kernel(const int* __restrict__ dst) {
    int i = blockIdx.x * blockDim.x + threadIdx.x;
    if (i < EE) atomicAdd(&g_deg[dst[i]], 1);
}
__global__ void scan_kernel() {
    __shared__ int partial[1024];
    const int CH = (NN + 1023) / 1024;
    int t = threadIdx.x;
    int base = t * CH;
    int s = 0;
    for (int i = 0; i < CH; i++) { int idx = base + i; if (idx < NN) s += g_deg[idx]; }
    partial[t] = s;
    __syncthreads();
    for (int off = 1; off < 1024; off <<= 1) {
        int v = (t >= off) ? partial[t - off] : 0;
        __syncthreads();
        partial[t] += v;
        __syncthreads();
    }
    int run = (t > 0) ? partial[t - 1] : 0;
    for (int i = 0; i < CH; i++) {
        int idx = base + i;
        if (idx < NN) { int d = g_deg[idx]; g_rowptr[idx] = run; run += d; g_deg[idx] = 0; }
    }
    if (t == 1023) g_rowptr[NN] = partial[1023];
}
__global__ void scatter_kernel(const int* __restrict__ src, const int* __restrict__ dst) {
    int i = blockIdx.x * blockDim.x + threadIdx.x;
    if (i >= EE) return;
    int d = dst[i];
    int pos = g_rowptr[d] + atomicAdd(&g_deg[d], 1);
    g_csr_src[pos] = src[i];
}

// ---------------- fused conversions ----------------
#define SPLIT_BLOCKS ((NN * IN_DIM / 4 + 255) / 256)
#define T1_BLOCKS    ((IN_DIM * F1 + 255) / 256)
#define T2_BLOCKS    ((F1 * OUTF + 255) / 256)

__global__ void prep_kernel(const float* __restrict__ x, const float* __restrict__ W1,
                            const float* __restrict__ W2) {
    int b = blockIdx.x;
    int t = threadIdx.x;
    if (b < SPLIT_BLOCKS) {
        int i4 = (b * 256 + t) * 4;
        if (i4 >= NN * IN_DIM) return;
        float4 v = *(const float4*)(x + i4);
        __nv_bfloat16 h0 = __float2bfloat16(v.x), h1 = __float2bfloat16(v.y);
        __nv_bfloat16 h2 = __float2bfloat16(v.z), h3 = __float2bfloat16(v.w);
        __nv_bfloat16 l0 = __float2bfloat16(v.x - __bfloat162float(h0));
        __nv_bfloat16 l1 = __float2bfloat16(v.y - __bfloat162float(h1));
        __nv_bfloat16 l2 = __float2bfloat16(v.z - __bfloat162float(h2));
        __nv_bfloat16 l3 = __float2bfloat16(v.w - __bfloat162float(h3));
        __nv_bfloat162* ph = (__nv_bfloat162*)(g_xhi + i4);
        __nv_bfloat162* pl = (__nv_bfloat162*)(g_xlo + i4);
        ph[0] = __halves2bfloat162(h0, h1); ph[1] = __halves2bfloat162(h2, h3);
        pl[0] = __halves2bfloat162(l0, l1); pl[1] = __halves2bfloat162(l2, l3);
    } else if (b < SPLIT_BLOCKS + T1_BLOCKS) {
        int i = (b - SPLIT_BLOCKS) * 256 + t;
        if (i >= IN_DIM * F1) return;
        int k = i / F1, n = i - k * F1;
        float v = W1[i];
        __nv_bfloat16 h = __float2bfloat16(v);
        g_w1t_hi[(size_t)n * IN_DIM + k] = h;
        g_w1t_lo[(size_t)n * IN_DIM + k] = __float2bfloat16(v - __bfloat162float(h));
    } else {
        int i = (b - SPLIT_BLOCKS - T1_BLOCKS) * 256 + t;
        if (i >= F1 * OUTF) return;
        int k = i / OUTF, n = i - k * OUTF;
        float v = W2[i];
        __nv_bfloat16 h = __float2bfloat16(v);
        g_w2t_hi[(size_t)n * F1 + k] = h;
        g_w2t_lo[(size_t)n * F1 + k] = __float2bfloat16(v - __bfloat162float(h));
    }
}

// ---------------- bf16 mma.sync GEMM (512 threads) + fused el/er epilogue ----------------
__device__ __forceinline__ void load_tile64_async(uint32_t sb, int smem_off,
    const __nv_bfloat16* __restrict__ g, int ldK, int kc,
    int row0, int rows, int rlim, int tid) {
    int units = rows * 8;
    for (int i = tid; i < units; i += 512) {
        int r = i >> 3, seg = i & 7;
        int gr = row0 + r;
        int ok = (gr < rlim);
        int sz = ok ? 16 : 0;
        const void* src = g + (size_t)(ok ? gr : 0) * ldK + kc + seg * 8;
        int off = r * 128 + seg * 16;
        off ^= (off >> 3) & 0x70;
        asm volatile("cp.async.cg.shared.global [%0], [%1], 16, %2;"
                     :: "r"(sb + smem_off + off), "l"(src), "r"(sz));
    }
}

// 16 warps: 4(m) x 4(n); warp tile 32 x (BN/4); MT=2 m16 tiles per warp.
template <int BN, int NSTAGE, int NH>
__global__ void __launch_bounds__(512) gemm_mma(
    const __nv_bfloat16* __restrict__ Ahi, const __nv_bfloat16* __restrict__ Alo,
    const __nv_bfloat16* __restrict__ Bhi, const __nv_bfloat16* __restrict__ Blo,
    float* __restrict__ C,
    const float* __restrict__ alv, const float* __restrict__ arv,
    float* __restrict__ el, float* __restrict__ er,
    int M, int Nc, int K) {
    extern __shared__ char smem[];
    constexpr int OFF_AH = 0;
    constexpr int OFF_AL = 16384;
    constexpr int OFF_BH = 32768;
    constexpr int OFF_BL = OFF_BH + BN * 128;
    constexpr int STAGE  = OFF_BL + BN * 128;
    constexpr int WN = BN / 4;
    constexpr int NT = WN / 8;

    const int tid = threadIdx.x;
    const int wid = tid >> 5;
    const int lane = tid & 31;
    const int wm = wid >> 2;      // 0..3, 32-row band
    const int wn = wid & 3;       // 0..3
    const int row0 = blockIdx.y * 128;
    const int col0 = blockIdx.x * BN;
    const int head = blockIdx.x;

    const uint32_t sb = smem_u32(smem);
    float* s_el = (float*)(smem + NSTAGE * STAGE);
    float* s_er = s_el + 128;

    if (tid < 128) { s_el[tid] = 0.f; s_er[tid] = 0.f; }

    float acc[2][NT][4];
#pragma unroll
    for (int i = 0; i < 2; i++)
#pragma unroll
        for (int j = 0; j < NT; j++)
#pragma unroll
            for (int q = 0; q < 4; q++) acc[i][j][q] = 0.f;

    const int a_r  = (lane & 15);
    const int a_kb = (lane >> 4) * 16;
    const int b_n  = (lane & 7) + ((lane >> 4) << 3);
    const int b_kb = ((lane >> 3) & 1) * 16;

    const int nchunks = K >> 6;

#pragma unroll
    for (int p = 0; p < NSTAGE - 1; p++) {
        if (p < nchunks) {
            uint32_t sp = sb + p * STAGE;
            int kc = p << 6;
            load_tile64_async(sp, OFF_AH, Ahi, K, kc, row0, 128, M, tid);
            load_tile64_async(sp, OFF_AL, Alo, K, kc, row0, 128, M, tid);
            load_tile64_async(sp, OFF_BH, Bhi, K, kc, col0, BN, Nc, tid);
            load_tile64_async(sp, OFF_BL, Blo, K, kc, col0, BN, Nc, tid);
            asm volatile("cp.async.commit_group;");
        }
    }

    for (int c = 0; c < nchunks; c++) {
        if (c >= nchunks - 1)
            asm volatile("cp.async.wait_group 0;");
        else if (NSTAGE >= 3 && c < nchunks - 2)
            asm volatile("cp.async.wait_group %0;" :: "n"(NSTAGE - 2));
        else
            asm volatile("cp.async.wait_group 1;");
        __syncthreads();

        if (c + NSTAGE - 1 < nchunks) {
            int cn = c + NSTAGE - 1;
            uint32_t sn = sb + (cn % NSTAGE) * STAGE;
            int kc = cn << 6;
            load_tile64_async(sn, OFF_AH, Ahi, K, kc, row0, 128, M, tid);
            load_tile64_async(sn, OFF_AL, Alo, K, kc, row0, 128, M, tid);
            load_tile64_async(sn, OFF_BH, Bhi, K, kc, col0, BN, Nc, tid);
            load_tile64_async(sn, OFF_BL, Blo, K, kc, col0, BN, Nc, tid);
            asm volatile("cp.async.commit_group;");
        }

        const uint32_t sc = sb + (c % NSTAGE) * STAGE;
#pragma unroll
        for (int kk = 0; kk < 64; kk += 16) {
            uint32_t ah[2][4], al4[2][4];
#pragma unroll
            for (int mt = 0; mt < 2; mt++) {
                int r = wm * 32 + mt * 16 + a_r;
                int off = r * 128 + kk * 2 + a_kb;
                ldsm_x4(ah[mt], sc + OFF_AH + swz(off));
                ldsm_x4(al4[mt], sc + OFF_AL + swz(off));
            }
            uint32_t bh[NT][2], bl[NT][2];
#pragma unroll
            for (int bt = 0; bt < NT / 2; bt++) {
                int n = wn * WN + bt * 16 + b_n;
                int off = n * 128 + kk * 2 + b_kb;
                uint32_t t4[4];
                ldsm_x4(t4, sc + OFF_BH + swz(off));
                bh[2 * bt][0] = t4[0]; bh[2 * bt][1] = t4[1];
                bh[2 * bt + 1][0] = t4[2]; bh[2 * bt + 1][1] = t4[3];
                ldsm_x4(t4, sc + OFF_BL + swz(off));
                bl[2 * bt][0] = t4[0]; bl[2 * bt][1] = t4[1];
                bl[2 * bt + 1][0] = t4[2]; bl[2 * bt + 1][1] = t4[3];
            }
#pragma unroll
            for (int mt = 0; mt < 2; mt++)
#pragma unroll
                for (int nt = 0; nt < NT; nt++) {
                    mma_bf16(acc[mt][nt], ah[mt], bh[nt]);
                    mma_bf16(acc[mt][nt], ah[mt], bl[nt]);
                    mma_bf16(acc[mt][nt], al4[mt], bh[nt]);
                }
        }
        __syncthreads();
    }

    float va[NT][2], vr[NT][2];
#pragma unroll
    for (int nt = 0; nt < NT; nt++) {
        int cL = wn * WN + nt * 8 + (lane & 3) * 2;
        va[nt][0] = alv[head * BN + cL];     va[nt][1] = alv[head * BN + cL + 1];
        vr[nt][0] = arv[head * BN + cL];     vr[nt][1] = arv[head * BN + cL + 1];
    }

#pragma unroll
    for (int mt = 0; mt < 2; mt++) {
        int rL0 = wm * 32 + mt * 16 + (lane >> 2);
        int m0 = row0 + rL0;
        float e0 = 0.f, r0 = 0.f, e1 = 0.f, r1 = 0.f;
#pragma unroll
        for (int nt = 0; nt < NT; nt++) {
            int n0 = col0 + wn * WN + nt * 8 + (lane & 3) * 2;
            if (m0 < M)
                *(float2*)(C + (size_t)m0 * Nc + n0) = make_float2(acc[mt][nt][0], acc[mt][nt][1]);
            if (m0 + 8 < M)
                *(float2*)(C + (size_t)(m0 + 8) * Nc + n0) = make_float2(acc[mt][nt][2], acc[mt][nt][3]);
            e0 += acc[mt][nt][0] * va[nt][0] + acc[mt][nt][1] * va[nt][1];
            r0 += acc[mt][nt][0] * vr[nt][0] + acc[mt][nt][1] * vr[nt][1];
            e1 += acc[mt][nt][2] * va[nt][0] + acc[mt][nt][3] * va[nt][1];
            r1 += acc[mt][nt][2] * vr[nt][0] + acc[mt][nt][3] * vr[nt][1];
        }
#pragma unroll
        for (int o = 1; o <= 2; o <<= 1) {
            e0 += __shfl_xor_sync(0xffffffffu, e0, o);
            r0 += __shfl_xor_sync(0xffffffffu, r0, o);
            e1 += __shfl_xor_sync(0xffffffffu, e1, o);
            r1 += __shfl_xor_sync(0xffffffffu, r1, o);
        }
        if ((lane & 3) == 0) {
            atomicAdd(&s_el[rL0], e0);
            atomicAdd(&s_er[rL0], r0);
            atomicAdd(&s_el[rL0 + 8], e1);
            atomicAdd(&s_er[rL0 + 8], r1);
        }
    }
    __syncthreads();
    if (tid < 128) {
        int node = row0 + tid;
        if (node < M) {
            el[node * NH + head] = s_el[tid];
            er[node * NH + head] = s_er[tid];
        }
    }
}

// ---------------- layer-1 aggregation ----------------
__global__ void agg1_kernel(const float* __restrict__ b1) {
    int node = (blockIdx.x * blockDim.x + threadIdx.x) >> 5;
    int lane = threadIdx.x & 31;
    if (node >= NN) return;
    int beg = g_rowptr[node], end = g_rowptr[node + 1];

    int hh = lane & 3;
    float er_hh = g_er1[node * 4 + hh];

    float m = -INFINITY;
    for (int j = beg + (lane >> 2); j < end; j += 8) {
        int s = g_csr_src[j];
        m = fmaxf(m, leaky(g_el1[s * 4 + hh] + er_hh));
    }
#pragma unroll
    for (int o = 4; o < 32; o <<= 1) m = fmaxf(m, __shfl_xor_sync(0xffffffffu, m, o));

    float ssum = 0.f;
    for (int j = beg + (lane >> 2); j < end; j += 8) {
        int s = g_csr_src[j];
        ssum += __expf(leaky(g_el1[s * 4 + hh] + er_hh) - m);
    }
#pragma unroll
    for (int o = 4; o < 32; o <<= 1) ssum += __shfl_xor_sync(0xffffffffu, ssum, o);

    int myhead = lane >> 3;
    float m_h = __shfl_sync(0xffffffffu, m, myhead);
    float s_h = __shfl_sync(0xffffffffu, ssum, myhead);
    float er_mh = g_er1[node * 4 + myhead];
    float inv_s = 1.f / s_h;

    float acc[16];
#pragma unroll
    for (int q = 0; q < 16; q++) acc[q] = 0.f;

    int j = beg;
    for (; j + 4 <= end; j += 4) {
        int s0 = g_csr_src[j];
        int s1 = g_csr_src[j + 1];
        int s2 = g_csr_src[j + 2];
        int s3 = g_csr_src[j + 3];
        float a0 = __expf(leaky(g_el1[s0 * 4 + myhead] + er_mh) - m_h) * inv_s;
        float a1 = __expf(leaky(g_el1[s1 * 4 + myhead] + er_mh) - m_h) * inv_s;
        float a2 = __expf(leaky(g_el1[s2 * 4 + myhead] + er_mh) - m_h) * inv_s;
        float a3 = __expf(leaky(g_el1[s3 * 4 + myhead] + er_mh) - m_h) * inv_s;
        const float4* f0 = (const float4*)(g_feat1 + (size_t)s0 * F1 + lane * 16);
        const float4* f1 = (const float4*)(g_feat1 + (size_t)s1 * F1 + lane * 16);
        const float4* f2 = (const float4*)(g_feat1 + (size_t)s2 * F1 + lane * 16);
        const float4* f3 = (const float4*)(g_feat1 + (size_t)s3 * F1 + lane * 16);
#pragma unroll
        for (int q = 0; q < 4; q++) {
            float4 v0 = f0[q];
            float4 v1 = f1[q];
            float4 v2 = f2[q];
            float4 v3 = f3[q];
            acc[q * 4 + 0] += a0 * v0.x + a1 * v1.x + a2 * v2.x + a3 * v3.x;
            acc[q * 4 + 1] += a0 * v0.y + a1 * v1.y + a2 * v2.y + a3 * v3.y;
            acc[q * 4 + 2] += a0 * v0.z + a1 * v1.z + a2 * v2.z + a3 * v3.z;
            acc[q * 4 + 3] += a0 * v0.w + a1 * v1.w + a2 * v2.w + a3 * v3.w;
        }
    }
    for (; j < end; j++) {
        int s0 = g_csr_src[j];
        float a0 = __expf(leaky(g_el1[s0 * 4 + myhead] + er_mh) - m_h) * inv_s;
        const float4* f0 = (const float4*)(g_feat1 + (size_t)s0 * F1 + lane * 16);
#pragma unroll
        for (int q = 0; q < 4; q++) {
            float4 v0 = f0[q];
            acc[q * 4 + 0] += a0 * v0.x;
            acc[q * 4 + 1] += a0 * v0.y;
            acc[q * 4 + 2] += a0 * v0.z;
            acc[q * 4 + 3] += a0 * v0.w;
        }
    }

    size_t obase = (size_t)node * F1 + lane * 16;
#pragma unroll
    for (int q = 0; q < 4; q++) {
        float vv[4];
#pragma unroll
        for (int u = 0; u < 4; u++) {
            float v = acc[q * 4 + u] + b1[lane * 16 + q * 4 + u];
            vv[u] = v > 0.f ? v : expm1f(v);
        }
        __nv_bfloat16 h0 = __float2bfloat16(vv[0]), h1 = __float2bfloat16(vv[1]);
        __nv_bfloat16 h2 = __float2bfloat16(vv[2]), h3 = __float2bfloat16(vv[3]);
        __nv_bfloat16 l0 = __float2bfloat16(vv[0] - __bfloat162float(h0));
        __nv_bfloat16 l1 = __float2bfloat16(vv[1] - __bfloat162float(h1));
        __nv_bfloat16 l2 = __float2bfloat16(vv[2] - __bfloat162float(h2));
        __nv_bfloat16 l3 = __float2bfloat16(vv[3] - __bfloat162float(h3));
        __nv_bfloat162* ph = (__nv_bfloat162*)(g_hhi + obase + q * 4);
        __nv_bfloat162* pl = (__nv_bfloat162*)(g_hlo + obase + q * 4);
        ph[0] = __halves2bfloat162(h0, h1); ph[1] = __halves2bfloat162(h2, h3);
        pl[0] = __halves2bfloat162(l0, l1); pl[1] = __halves2bfloat162(l2, l3);
    }
}

// ---------------- layer-2 aggregation ----------------
__global__ void agg2_kernel(const float* __restrict__ b2, float* __restrict__ out) {
    int node = (blockIdx.x * blockDim.x + threadIdx.x) >> 5;
    int lane = threadIdx.x & 31;
    if (node >= NN) return;
    int beg = g_rowptr[node], end = g_rowptr[node + 1];

    float er_n = g_er2[node];

    float m = -INFINITY;
    for (int j = beg + lane; j < end; j += 32)
        m = fmaxf(m, leaky(g_el2[g_csr_src[j]] + er_n));
#pragma unroll
    for (int o = 16; o > 0; o >>= 1) m = fmaxf(m, __shfl_xor_sync(0xffffffffu, m, o));

    float ssum = 0.f;
    for (int j = beg + lane; j < end; j += 32)
        ssum += __expf(leaky(g_el2[g_csr_src[j]] + er_n) - m);
#pragma unroll
    for (int o = 16; o > 0; o >>= 1) ssum += __shfl_xor_sync(0xffffffffu, ssum, o);
    float inv_s = 1.f / ssum;

    float acc0 = 0.f, acc1 = 0.f;
    int j = beg;
    for (; j + 4 <= end; j += 4) {
        int s0 = g_csr_src[j];
        int s1 = g_csr_src[j + 1];
        int s2 = g_csr_src[j + 2];
        int s3 = g_csr_src[j + 3];
        float a0 = __expf(leaky(g_el2[s0] + er_n) - m) * inv_s;
        float a1 = __expf(leaky(g_el2[s1] + er_n) - m) * inv_s;
        float a2 = __expf(leaky(g_el2[s2] + er_n) - m) * inv_s;
        float a3 = __expf(leaky(g_el2[s3] + er_n) - m) * inv_s;
        float2 v0 = *(const float2*)(g_feat2 + (size_t)s0 * OUTF + lane * 2);
        float2 v1 = *(const float2*)(g_feat2 + (size_t)s1 * OUTF + lane * 2);
        float2 v2 = *(const float2*)(g_feat2 + (size_t)s2 * OUTF + lane * 2);
        float2 v3 = *(const float2*)(g_feat2 + (size_t)s3 * OUTF + lane * 2);
        acc0 += a0 * v0.x + a1 * v1.x + a2 * v2.x + a3 * v3.x;
        acc1 += a0 * v0.y + a1 * v1.y + a2 * v2.y + a3 * v3.y;
    }
    for (; j < end; j++) {
        int s0 = g_csr_src[j];
        float a0 = __expf(leaky(g_el2[s0] + er_n) - m) * inv_s;
        float2 v0 = *(const float2*)(g_feat2 + (size_t)s0 * OUTF + lane * 2);
        acc0 += a0 * v0.x;
        acc1 += a0 * v0.y;
    }
    float2 o2;
    o2.x = acc0 + b2[lane * 2 + 0];
    o2.y = acc1 + b2[lane * 2 + 1];
    *(float2*)(out + (size_t)node * OUTF + lane * 2) = o2;
}

// ---------------- host launch ----------------
extern "C" void kernel_launch(void* const* d_in, const int* in_sizes, int n_in,
                              void* d_out, int out_size) {
    const float* x   = (const float*)d_in[0];
    const int*   src = (const int*)d_in[1];
    const int*   dst = (const int*)d_in[2];
    const float* W1  = (const float*)d_in[3];
    const float* al1 = (const float*)d_in[4];
    const float* ar1 = (const float*)d_in[5];
    const float* b1  = (const float*)d_in[6];
    const float* W2  = (const float*)d_in[7];
    const float* al2 = (const float*)d_in[8];
    const float* ar2 = (const float*)d_in[9];
    const float* b2  = (const float*)d_in[10];
    float* out = (float*)d_out;

    void *p_feat1, *p_feat2, *p_el1, *p_er1, *p_el2, *p_er2;
    void *p_xhi, *p_xlo, *p_hhi, *p_hlo, *p_w1h, *p_w1l, *p_w2h, *p_w2l;
    cudaGetSymbolAddress(&p_feat1, g_feat1);
    cudaGetSymbolAddress(&p_feat2, g_feat2);
    cudaGetSymbolAddress(&p_el1, g_el1);
    cudaGetSymbolAddress(&p_er1, g_er1);
    cudaGetSymbolAddress(&p_el2, g_el2);
    cudaGetSymbolAddress(&p_er2, g_er2);
    cudaGetSymbolAddress(&p_xhi, g_xhi);
    cudaGetSymbolAddress(&p_xlo, g_xlo);
    cudaGetSymbolAddress(&p_hhi, g_hhi);
    cudaGetSymbolAddress(&p_hlo, g_hlo);
    cudaGetSymbolAddress(&p_w1h, g_w1t_hi);
    cudaGetSymbolAddress(&p_w1l, g_w1t_lo);
    cudaGetSymbolAddress(&p_w2h, g_w2t_hi);
    cudaGetSymbolAddress(&p_w2l, g_w2t_lo);

    const int SMEM1 = 3 * 65536 + 1024;
    const int SMEM2 = 3 * 49152 + 1024;
    static bool attrs_set = false;
    if (!attrs_set) {
        cudaFuncSetAttribute(gemm_mma<128, 3, H0>, cudaFuncAttributeMaxDynamicSharedMemorySize, SMEM1);
        cudaFuncSetAttribute(gemm_mma<64, 3, 1>,   cudaFuncAttributeMaxDynamicSharedMemorySize, SMEM2);
        attrs_set = true;
    }

    static cudaStream_t s2 = nullptr;
    static cudaEvent_t evFork = nullptr, evJoin = nullptr;
    if (!s2) {
        cudaStreamCreateWithFlags(&s2, cudaStreamNonBlocking);
        cudaEventCreateWithFlags(&evFork, cudaEventDisableTiming);
        cudaEventCreateWithFlags(&evJoin, cudaEventDisableTiming);
    }

    cudaEventRecord(evFork, 0);
    cudaStreamWaitEvent(s2, evFork, 0);

    zero_deg_kernel<<<(NN + 255) / 256, 256, 0, s2>>>();                   // #0
    count_deg_kernel<<<(EE + 255) / 256, 256, 0, s2>>>(dst);               // #1

    prep_kernel<<<SPLIT_BLOCKS + T1_BLOCKS + T2_BLOCKS, 256>>>(x, W1, W2); // #2
    {
        dim3 grid(F1 / 128, (NN + 127) / 128);
        gemm_mma<128, 3, H0><<<grid, 512, SMEM1>>>((const __nv_bfloat16*)p_xhi,     // #3
                                                   (const __nv_bfloat16*)p_xlo,
                                                   (const __nv_bfloat16*)p_w1h,
                                                   (const __nv_bfloat16*)p_w1l,
                                                   (float*)p_feat1, al1, ar1,
                                                   (float*)p_el1, (float*)p_er1,
                                                   NN, F1, IN_DIM);
    }

    scan_kernel<<<1, 1024, 0, s2>>>();                                     // #4
    scatter_kernel<<<(EE + 255) / 256, 256, 0, s2>>>(src, dst);            // #5
    cudaEventRecord(evJoin, s2);

    cudaStreamWaitEvent(0, evJoin, 0);
    agg1_kernel<<<(NN * 32 + 255) / 256, 256>>>(b1);                       // #6

    {
        dim3 grid(1, (NN + 127) / 128);
        gemm_mma<64, 3, 1><<<grid, 512, SMEM2>>>((const __nv_bfloat16*)p_hhi,       // #7
                                                 (const __nv_bfloat16*)p_hlo,
                                                 (const __nv_bfloat16*)p_w2h,
                                                 (const __nv_bfloat16*)p_w2l,
                                                 (float*)p_feat2, al2, ar2,
                                                 (float*)p_el2, (float*)p_er2,
                                                 NN, OUTF, F1);
    }
    agg2_kernel<<<(NN * 32 + 255) / 256, 256>>>(b2, out);                  // #8
}

// round 10
// speedup vs baseline: 1.0345x; 1.0345x over previous
#include <cuda_runtime.h>
#include <cuda_bf16.h>
#include <cstdint>

#define NN      20000
#define EE      320000
#define IN_DIM  256
#define H0      4
#define D0      128
#define F1      512     // H0*D0
#define OUTF    64

// ---------------- device scratch (allocation-free contract) ----------------
__device__ float g_feat1[(size_t)NN * F1];
__device__ float g_feat2[(size_t)NN * OUTF];
__device__ __nv_bfloat16 g_xhi[(size_t)NN * IN_DIM];
__device__ __nv_bfloat16 g_xlo[(size_t)NN * IN_DIM];
__device__ __nv_bfloat16 g_hhi[(size_t)NN * F1];
__device__ __nv_bfloat16 g_hlo[(size_t)NN * F1];
__device__ __nv_bfloat16 g_w1t_hi[(size_t)F1 * IN_DIM];
__device__ __nv_bfloat16 g_w1t_lo[(size_t)F1 * IN_DIM];
__device__ __nv_bfloat16 g_w2t_hi[(size_t)OUTF * F1];
__device__ __nv_bfloat16 g_w2t_lo[(size_t)OUTF * F1];
__device__ float g_el1[NN * H0];
__device__ float g_er1[NN * H0];
__device__ float g_el2[NN];
__device__ float g_er2[NN];
__device__ int   g_deg[NN];
__device__ int   g_rowptr[NN + 1];
__device__ int   g_csr_src[EE];

// ---------------- helpers ----------------
__device__ __forceinline__ uint32_t smem_u32(const void* p) {
    uint32_t a;
    asm("{ .reg .u64 t; cvta.to.shared.u64 t, %1; cvt.u32.u64 %0, t; }" : "=r"(a) : "l"(p));
    return a;
}
__device__ __forceinline__ void ldsm_x4(uint32_t* r, uint32_t addr) {
    asm volatile("ldmatrix.sync.aligned.m8n8.x4.shared.b16 {%0,%1,%2,%3}, [%4];"
                 : "=r"(r[0]), "=r"(r[1]), "=r"(r[2]), "=r"(r[3]) : "r"(addr));
}
__device__ __forceinline__ void mma_bf16(float* c, const uint32_t* a, const uint32_t* b) {
    asm volatile(
        "mma.sync.aligned.m16n8k16.row.col.f32.bf16.bf16.f32 "
        "{%0,%1,%2,%3}, {%4,%5,%6,%7}, {%8,%9}, {%0,%1,%2,%3};"
        : "+f"(c[0]), "+f"(c[1]), "+f"(c[2]), "+f"(c[3])
        : "r"(a[0]), "r"(a[1]), "r"(a[2]), "r"(a[3]), "r"(b[0]), "r"(b[1]));
}
__device__ __forceinline__ uint32_t swz(int off) { return off ^ ((off >> 3) & 0x70); }
__device__ __forceinline__ float leaky(float e) { return fmaxf(e, 0.2f * e); }

// ---------------- CSR build ----------------
__global__ void zero_deg_kernel() {
    int i = blockIdx.x * blockDim.x + threadIdx.x;
    if (i < NN) g_deg[i] = 0;
}
__global__ void count_deg_kernel(const int* __restrict__ dst) {
    int i = blockIdx.x * blockDim.x + threadIdx.x;
    if (i < EE) atomicAdd(&g_deg[dst[i]], 1);
}
__global__ void scan_kernel() {
    __shared__ int partial[1024];
    const int CH = (NN + 1023) / 1024;
    int t = threadIdx.x;
    int base = t * CH;
    int s = 0;
    for (int i = 0; i < CH; i++) { int idx = base + i; if (idx < NN) s += g_deg[idx]; }
    partial[t] = s;
    __syncthreads();
    for (int off = 1; off < 1024; off <<= 1) {
        int v = (t >= off) ? partial[t - off] : 0;
        __syncthreads();
        partial[t] += v;
        __syncthreads();
    }
    int run = (t > 0) ? partial[t - 1] : 0;
    for (int i = 0; i < CH; i++) {
        int idx = base + i;
        if (idx < NN) { int d = g_deg[idx]; g_rowptr[idx] = run; run += d; g_deg[idx] = 0; }
    }
    if (t == 1023) g_rowptr[NN] = partial[1023];
}
__global__ void scatter_kernel(const int* __restrict__ src, const int* __restrict__ dst) {
    int i = blockIdx.x * blockDim.x + threadIdx.x;
    if (i >= EE) return;
    int d = dst[i];
    int pos = g_rowptr[d] + atomicAdd(&g_deg[d], 1);
    g_csr_src[pos] = src[i];
}

// ---------------- fused conversions ----------------
#define SPLIT_BLOCKS ((NN * IN_DIM / 4 + 255) / 256)
#define T1_BLOCKS    ((IN_DIM * F1 + 255) / 256)
#define T2_BLOCKS    ((F1 * OUTF + 255) / 256)

__global__ void prep_kernel(const float* __restrict__ x, const float* __restrict__ W1,
                            const float* __restrict__ W2) {
    int b = blockIdx.x;
    int t = threadIdx.x;
    if (b < SPLIT_BLOCKS) {
        int i4 = (b * 256 + t) * 4;
        if (i4 >= NN * IN_DIM) return;
        float4 v = *(const float4*)(x + i4);
        __nv_bfloat16 h0 = __float2bfloat16(v.x), h1 = __float2bfloat16(v.y);
        __nv_bfloat16 h2 = __float2bfloat16(v.z), h3 = __float2bfloat16(v.w);
        __nv_bfloat16 l0 = __float2bfloat16(v.x - __bfloat162float(h0));
        __nv_bfloat16 l1 = __float2bfloat16(v.y - __bfloat162float(h1));
        __nv_bfloat16 l2 = __float2bfloat16(v.z - __bfloat162float(h2));
        __nv_bfloat16 l3 = __float2bfloat16(v.w - __bfloat162float(h3));
        __nv_bfloat162* ph = (__nv_bfloat162*)(g_xhi + i4);
        __nv_bfloat162* pl = (__nv_bfloat162*)(g_xlo + i4);
        ph[0] = __halves2bfloat162(h0, h1); ph[1] = __halves2bfloat162(h2, h3);
        pl[0] = __halves2bfloat162(l0, l1); pl[1] = __halves2bfloat162(l2, l3);
    } else if (b < SPLIT_BLOCKS + T1_BLOCKS) {
        int i = (b - SPLIT_BLOCKS) * 256 + t;
        if (i >= IN_DIM * F1) return;
        int k = i / F1, n = i - k * F1;
        float v = W1[i];
        __nv_bfloat16 h = __float2bfloat16(v);
        g_w1t_hi[(size_t)n * IN_DIM + k] = h;
        g_w1t_lo[(size_t)n * IN_DIM + k] = __float2bfloat16(v - __bfloat162float(h));
    } else {
        int i = (b - SPLIT_BLOCKS - T1_BLOCKS) * 256 + t;
        if (i >= F1 * OUTF) return;
        int k = i / OUTF, n = i - k * OUTF;
        float v = W2[i];
        __nv_bfloat16 h = __float2bfloat16(v);
        g_w2t_hi[(size_t)n * F1 + k] = h;
        g_w2t_lo[(size_t)n * F1 + k] = __float2bfloat16(v - __bfloat162float(h));
    }
}

// ---------------- bf16 mma.sync GEMM (512 threads) + fused el/er epilogue ----------------
__device__ __forceinline__ void load_tile64_async(uint32_t sb, int smem_off,
    const __nv_bfloat16* __restrict__ g, int ldK, int kc,
    int row0, int rows, int rlim, int tid) {
    int units = rows * 8;
    for (int i = tid; i < units; i += 512) {
        int r = i >> 3, seg = i & 7;
        int gr = row0 + r;
        int ok = (gr < rlim);
        int sz = ok ? 16 : 0;
        const void* src = g + (size_t)(ok ? gr : 0) * ldK + kc + seg * 8;
        int off = r * 128 + seg * 16;
        off ^= (off >> 3) & 0x70;
        asm volatile("cp.async.cg.shared.global [%0], [%1], 16, %2;"
                     :: "r"(sb + smem_off + off), "l"(src), "r"(sz));
    }
}

// 16 warps: 4(m) x 4(n); warp tile 32 x (BN/4); MT=2 m16 tiles per warp.
template <int BN, int NSTAGE, int NH>
__global__ void __launch_bounds__(512) gemm_mma(
    const __nv_bfloat16* __restrict__ Ahi, const __nv_bfloat16* __restrict__ Alo,
    const __nv_bfloat16* __restrict__ Bhi, const __nv_bfloat16* __restrict__ Blo,
    float* __restrict__ C,
    const float* __restrict__ alv, const float* __restrict__ arv,
    float* __restrict__ el, float* __restrict__ er,
    int M, int Nc, int K) {
    extern __shared__ char smem[];
    constexpr int OFF_AH = 0;
    constexpr int OFF_AL = 16384;
    constexpr int OFF_BH = 32768;
    constexpr int OFF_BL = OFF_BH + BN * 128;
    constexpr int STAGE  = OFF_BL + BN * 128;
    constexpr int WN = BN / 4;
    constexpr int NT = WN / 8;

    const int tid = threadIdx.x;
    const int wid = tid >> 5;
    const int lane = tid & 31;
    const int wm = wid >> 2;      // 0..3, 32-row band
    const int wn = wid & 3;       // 0..3
    const int row0 = blockIdx.y * 128;
    const int col0 = blockIdx.x * BN;
    const int head = blockIdx.x;

    const uint32_t sb = smem_u32(smem);
    float* s_el = (float*)(smem + NSTAGE * STAGE);
    float* s_er = s_el + 128;

    if (tid < 128) { s_el[tid] = 0.f; s_er[tid] = 0.f; }

    float acc[2][NT][4];
#pragma unroll
    for (int i = 0; i < 2; i++)
#pragma unroll
        for (int j = 0; j < NT; j++)
#pragma unroll
            for (int q = 0; q < 4; q++) acc[i][j][q] = 0.f;

    const int a_r  = (lane & 15);
    const int a_kb = (lane >> 4) * 16;
    const int b_n  = (lane & 7) + ((lane >> 4) << 3);
    const int b_kb = ((lane >> 3) & 1) * 16;

    const int nchunks = K >> 6;

#pragma unroll
    for (int p = 0; p < NSTAGE - 1; p++) {
        if (p < nchunks) {
            uint32_t sp = sb + p * STAGE;
            int kc = p << 6;
            load_tile64_async(sp, OFF_AH, Ahi, K, kc, row0, 128, M, tid);
            load_tile64_async(sp, OFF_AL, Alo, K, kc, row0, 128, M, tid);
            load_tile64_async(sp, OFF_BH, Bhi, K, kc, col0, BN, Nc, tid);
            load_tile64_async(sp, OFF_BL, Blo, K, kc, col0, BN, Nc, tid);
            asm volatile("cp.async.commit_group;");
        }
    }

    for (int c = 0; c < nchunks; c++) {
        if (c >= nchunks - 1)
            asm volatile("cp.async.wait_group 0;");
        else if (NSTAGE >= 3 && c < nchunks - 2)
            asm volatile("cp.async.wait_group %0;" :: "n"(NSTAGE - 2));
        else
            asm volatile("cp.async.wait_group 1;");
        __syncthreads();

        if (c + NSTAGE - 1 < nchunks) {
            int cn = c + NSTAGE - 1;
            uint32_t sn = sb + (cn % NSTAGE) * STAGE;
            int kc = cn << 6;
            load_tile64_async(sn, OFF_AH, Ahi, K, kc, row0, 128, M, tid);
            load_tile64_async(sn, OFF_AL, Alo, K, kc, row0, 128, M, tid);
            load_tile64_async(sn, OFF_BH, Bhi, K, kc, col0, BN, Nc, tid);
            load_tile64_async(sn, OFF_BL, Blo, K, kc, col0, BN, Nc, tid);
            asm volatile("cp.async.commit_group;");
        }

        const uint32_t sc = sb + (c % NSTAGE) * STAGE;
#pragma unroll
        for (int kk = 0; kk < 64; kk += 16) {
            uint32_t ah[2][4], al4[2][4];
#pragma unroll
            for (int mt = 0; mt < 2; mt++) {
                int r = wm * 32 + mt * 16 + a_r;
                int off = r * 128 + kk * 2 + a_kb;
                ldsm_x4(ah[mt], sc + OFF_AH + swz(off));
                ldsm_x4(al4[mt], sc + OFF_AL + swz(off));
            }
            uint32_t bh[NT][2], bl[NT][2];
#pragma unroll
            for (int bt = 0; bt < NT / 2; bt++) {
                int n = wn * WN + bt * 16 + b_n;
                int off = n * 128 + kk * 2 + b_kb;
                uint32_t t4[4];
                ldsm_x4(t4, sc + OFF_BH + swz(off));
                bh[2 * bt][0] = t4[0]; bh[2 * bt][1] = t4[1];
                bh[2 * bt + 1][0] = t4[2]; bh[2 * bt + 1][1] = t4[3];
                ldsm_x4(t4, sc + OFF_BL + swz(off));
                bl[2 * bt][0] = t4[0]; bl[2 * bt][1] = t4[1];
                bl[2 * bt + 1][0] = t4[2]; bl[2 * bt + 1][1] = t4[3];
            }
#pragma unroll
            for (int mt = 0; mt < 2; mt++)
#pragma unroll
                for (int nt = 0; nt < NT; nt++) {
                    mma_bf16(acc[mt][nt], ah[mt], bh[nt]);
                    mma_bf16(acc[mt][nt], ah[mt], bl[nt]);
                    mma_bf16(acc[mt][nt], al4[mt], bh[nt]);
                }
        }
        __syncthreads();
    }

    float va[NT][2], vr[NT][2];
#pragma unroll
    for (int nt = 0; nt < NT; nt++) {
        int cL = wn * WN + nt * 8 + (lane & 3) * 2;
        va[nt][0] = alv[head * BN + cL];     va[nt][1] = alv[head * BN + cL + 1];
        vr[nt][0] = arv[head * BN + cL];     vr[nt][1] = arv[head * BN + cL + 1];
    }

#pragma unroll
    for (int mt = 0; mt < 2; mt++) {
        int rL0 = wm * 32 + mt * 16 + (lane >> 2);
        int m0 = row0 + rL0;
        float e0 = 0.f, r0 = 0.f, e1 = 0.f, r1 = 0.f;
#pragma unroll
        for (int nt = 0; nt < NT; nt++) {
            int n0 = col0 + wn * WN + nt * 8 + (lane & 3) * 2;
            if (m0 < M)
                *(float2*)(C + (size_t)m0 * Nc + n0) = make_float2(acc[mt][nt][0], acc[mt][nt][1]);
            if (m0 + 8 < M)
                *(float2*)(C + (size_t)(m0 + 8) * Nc + n0) = make_float2(acc[mt][nt][2], acc[mt][nt][3]);
            e0 += acc[mt][nt][0] * va[nt][0] + acc[mt][nt][1] * va[nt][1];
            r0 += acc[mt][nt][0] * vr[nt][0] + acc[mt][nt][1] * vr[nt][1];
            e1 += acc[mt][nt][2] * va[nt][0] + acc[mt][nt][3] * va[nt][1];
            r1 += acc[mt][nt][2] * vr[nt][0] + acc[mt][nt][3] * vr[nt][1];
        }
#pragma unroll
        for (int o = 1; o <= 2; o <<= 1) {
            e0 += __shfl_xor_sync(0xffffffffu, e0, o);
            r0 += __shfl_xor_sync(0xffffffffu, r0, o);
            e1 += __shfl_xor_sync(0xffffffffu, e1, o);
            r1 += __shfl_xor_sync(0xffffffffu, r1, o);
        }
        if ((lane & 3) == 0) {
            atomicAdd(&s_el[rL0], e0);
            atomicAdd(&s_er[rL0], r0);
            atomicAdd(&s_el[rL0 + 8], e1);
            atomicAdd(&s_er[rL0 + 8], r1);
        }
    }
    __syncthreads();
    if (tid < 128) {
        int node = row0 + tid;
        if (node < M) {
            el[node * NH + head] = s_el[tid];
            er[node * NH + head] = s_er[tid];
        }
    }
}

// ---------------- layer-1 aggregation ----------------
__global__ void agg1_kernel(const float* __restrict__ b1) {
    int node = (blockIdx.x * blockDim.x + threadIdx.x) >> 5;
    int lane = threadIdx.x & 31;
    if (node >= NN) return;
    int beg = g_rowptr[node], end = g_rowptr[node + 1];

    int hh = lane & 3;
    float er_hh = g_er1[node * 4 + hh];

    float m = -INFINITY;
    for (int j = beg + (lane >> 2); j < end; j += 8) {
        int s = g_csr_src[j];
        m = fmaxf(m, leaky(g_el1[s * 4 + hh] + er_hh));
    }
#pragma unroll
    for (int o = 4; o < 32; o <<= 1) m = fmaxf(m, __shfl_xor_sync(0xffffffffu, m, o));

    float ssum = 0.f;
    for (int j = beg + (lane >> 2); j < end; j += 8) {
        int s = g_csr_src[j];
        ssum += __expf(leaky(g_el1[s * 4 + hh] + er_hh) - m);
    }
#pragma unroll
    for (int o = 4; o < 32; o <<= 1) ssum += __shfl_xor_sync(0xffffffffu, ssum, o);

    int myhead = lane >> 3;
    float m_h = __shfl_sync(0xffffffffu, m, myhead);
    float s_h = __shfl_sync(0xffffffffu, ssum, myhead);
    float er_mh = g_er1[node * 4 + myhead];
    float inv_s = 1.f / s_h;

    float acc[16];
#pragma unroll
    for (int q = 0; q < 16; q++) acc[q] = 0.f;

    int j = beg;
    for (; j + 4 <= end; j += 4) {
        int s0 = g_csr_src[j];
        int s1 = g_csr_src[j + 1];
        int s2 = g_csr_src[j + 2];
        int s3 = g_csr_src[j + 3];
        float a0 = __expf(leaky(g_el1[s0 * 4 + myhead] + er_mh) - m_h) * inv_s;
        float a1 = __expf(leaky(g_el1[s1 * 4 + myhead] + er_mh) - m_h) * inv_s;
        float a2 = __expf(leaky(g_el1[s2 * 4 + myhead] + er_mh) - m_h) * inv_s;
        float a3 = __expf(leaky(g_el1[s3 * 4 + myhead] + er_mh) - m_h) * inv_s;
        const float4* f0 = (const float4*)(g_feat1 + (size_t)s0 * F1 + lane * 16);
        const float4* f1 = (const float4*)(g_feat1 + (size_t)s1 * F1 + lane * 16);
        const float4* f2 = (const float4*)(g_feat1 + (size_t)s2 * F1 + lane * 16);
        const float4* f3 = (const float4*)(g_feat1 + (size_t)s3 * F1 + lane * 16);
#pragma unroll
        for (int q = 0; q < 4; q++) {
            float4 v0 = f0[q];
            float4 v1 = f1[q];
            float4 v2 = f2[q];
            float4 v3 = f3[q];
            acc[q * 4 + 0] += a0 * v0.x + a1 * v1.x + a2 * v2.x + a3 * v3.x;
            acc[q * 4 + 1] += a0 * v0.y + a1 * v1.y + a2 * v2.y + a3 * v3.y;
            acc[q * 4 + 2] += a0 * v0.z + a1 * v1.z + a2 * v2.z + a3 * v3.z;
            acc[q * 4 + 3] += a0 * v0.w + a1 * v1.w + a2 * v2.w + a3 * v3.w;
        }
    }
    for (; j < end; j++) {
        int s0 = g_csr_src[j];
        float a0 = __expf(leaky(g_el1[s0 * 4 + myhead] + er_mh) - m_h) * inv_s;
        const float4* f0 = (const float4*)(g_feat1 + (size_t)s0 * F1 + lane * 16);
#pragma unroll
        for (int q = 0; q < 4; q++) {
            float4 v0 = f0[q];
            acc[q * 4 + 0] += a0 * v0.x;
            acc[q * 4 + 1] += a0 * v0.y;
            acc[q * 4 + 2] += a0 * v0.z;
            acc[q * 4 + 3] += a0 * v0.w;
        }
    }

    size_t obase = (size_t)node * F1 + lane * 16;
#pragma unroll
    for (int q = 0; q < 4; q++) {
        float vv[4];
#pragma unroll
        for (int u = 0; u < 4; u++) {
            float v = acc[q * 4 + u] + b1[lane * 16 + q * 4 + u];
            vv[u] = v > 0.f ? v : expm1f(v);
        }
        __nv_bfloat16 h0 = __float2bfloat16(vv[0]), h1 = __float2bfloat16(vv[1]);
        __nv_bfloat16 h2 = __float2bfloat16(vv[2]), h3 = __float2bfloat16(vv[3]);
        __nv_bfloat16 l0 = __float2bfloat16(vv[0] - __bfloat162float(h0));
        __nv_bfloat16 l1 = __float2bfloat16(vv[1] - __bfloat162float(h1));
        __nv_bfloat16 l2 = __float2bfloat16(vv[2] - __bfloat162float(h2));
        __nv_bfloat16 l3 = __float2bfloat16(vv[3] - __bfloat162float(h3));
        __nv_bfloat162* ph = (__nv_bfloat162*)(g_hhi + obase + q * 4);
        __nv_bfloat162* pl = (__nv_bfloat162*)(g_hlo + obase + q * 4);
        ph[0] = __halves2bfloat162(h0, h1); ph[1] = __halves2bfloat162(h2, h3);
        pl[0] = __halves2bfloat162(l0, l1); pl[1] = __halves2bfloat162(l2, l3);
    }
}

// ---------------- layer-2 aggregation ----------------
__global__ void agg2_kernel(const float* __restrict__ b2, float* __restrict__ out) {
    int node = (blockIdx.x * blockDim.x + threadIdx.x) >> 5;
    int lane = threadIdx.x & 31;
    if (node >= NN) return;
    int beg = g_rowptr[node], end = g_rowptr[node + 1];

    float er_n = g_er2[node];

    float m = -INFINITY;
    for (int j = beg + lane; j < end; j += 32)
        m = fmaxf(m, leaky(g_el2[g_csr_src[j]] + er_n));
#pragma unroll
    for (int o = 16; o > 0; o >>= 1) m = fmaxf(m, __shfl_xor_sync(0xffffffffu, m, o));

    float ssum = 0.f;
    for (int j = beg + lane; j < end; j += 32)
        ssum += __expf(leaky(g_el2[g_csr_src[j]] + er_n) - m);
#pragma unroll
    for (int o = 16; o > 0; o >>= 1) ssum += __shfl_xor_sync(0xffffffffu, ssum, o);
    float inv_s = 1.f / ssum;

    float acc0 = 0.f, acc1 = 0.f;
    int j = beg;
    for (; j + 4 <= end; j += 4) {
        int s0 = g_csr_src[j];
        int s1 = g_csr_src[j + 1];
        int s2 = g_csr_src[j + 2];
        int s3 = g_csr_src[j + 3];
        float a0 = __expf(leaky(g_el2[s0] + er_n) - m) * inv_s;
        float a1 = __expf(leaky(g_el2[s1] + er_n) - m) * inv_s;
        float a2 = __expf(leaky(g_el2[s2] + er_n) - m) * inv_s;
        float a3 = __expf(leaky(g_el2[s3] + er_n) - m) * inv_s;
        float2 v0 = *(const float2*)(g_feat2 + (size_t)s0 * OUTF + lane * 2);
        float2 v1 = *(const float2*)(g_feat2 + (size_t)s1 * OUTF + lane * 2);
        float2 v2 = *(const float2*)(g_feat2 + (size_t)s2 * OUTF + lane * 2);
        float2 v3 = *(const float2*)(g_feat2 + (size_t)s3 * OUTF + lane * 2);
        acc0 += a0 * v0.x + a1 * v1.x + a2 * v2.x + a3 * v3.x;
        acc1 += a0 * v0.y + a1 * v1.y + a2 * v2.y + a3 * v3.y;
    }
    for (; j < end; j++) {
        int s0 = g_csr_src[j];
        float a0 = __expf(leaky(g_el2[s0] + er_n) - m) * inv_s;
        float2 v0 = *(const float2*)(g_feat2 + (size_t)s0 * OUTF + lane * 2);
        acc0 += a0 * v0.x;
        acc1 += a0 * v0.y;
    }
    float2 o2;
    o2.x = acc0 + b2[lane * 2 + 0];
    o2.y = acc1 + b2[lane * 2 + 1];
    *(float2*)(out + (size_t)node * OUTF + lane * 2) = o2;
}

// ---------------- host launch ----------------
extern "C" void kernel_launch(void* const* d_in, const int* in_sizes, int n_in,
                              void* d_out, int out_size) {
    const float* x   = (const float*)d_in[0];
    const int*   src = (const int*)d_in[1];
    const int*   dst = (const int*)d_in[2];
    const float* W1  = (const float*)d_in[3];
    const float* al1 = (const float*)d_in[4];
    const float* ar1 = (const float*)d_in[5];
    const float* b1  = (const float*)d_in[6];
    const float* W2  = (const float*)d_in[7];
    const float* al2 = (const float*)d_in[8];
    const float* ar2 = (const float*)d_in[9];
    const float* b2  = (const float*)d_in[10];
    float* out = (float*)d_out;

    void *p_feat1, *p_feat2, *p_el1, *p_er1, *p_el2, *p_er2;
    void *p_xhi, *p_xlo, *p_hhi, *p_hlo, *p_w1h, *p_w1l, *p_w2h, *p_w2l;
    cudaGetSymbolAddress(&p_feat1, g_feat1);
    cudaGetSymbolAddress(&p_feat2, g_feat2);
    cudaGetSymbolAddress(&p_el1, g_el1);
    cudaGetSymbolAddress(&p_er1, g_er1);
    cudaGetSymbolAddress(&p_el2, g_el2);
    cudaGetSymbolAddress(&p_er2, g_er2);
    cudaGetSymbolAddress(&p_xhi, g_xhi);
    cudaGetSymbolAddress(&p_xlo, g_xlo);
    cudaGetSymbolAddress(&p_hhi, g_hhi);
    cudaGetSymbolAddress(&p_hlo, g_hlo);
    cudaGetSymbolAddress(&p_w1h, g_w1t_hi);
    cudaGetSymbolAddress(&p_w1l, g_w1t_lo);
    cudaGetSymbolAddress(&p_w2h, g_w2t_hi);
    cudaGetSymbolAddress(&p_w2l, g_w2t_lo);

    const int SMEM1 = 3 * 65536 + 1024;
    const int SMEM2 = 3 * 49152 + 1024;
    static bool attrs_set = false;
    if (!attrs_set) {
        cudaFuncSetAttribute(gemm_mma<128, 3, H0>, cudaFuncAttributeMaxDynamicSharedMemorySize, SMEM1);
        cudaFuncSetAttribute(gemm_mma<64, 3, 1>,   cudaFuncAttributeMaxDynamicSharedMemorySize, SMEM2);
        attrs_set = true;
    }

    static cudaStream_t s2 = nullptr;
    static cudaEvent_t evFork = nullptr, evJoin = nullptr;
    if (!s2) {
        cudaStreamCreateWithFlags(&s2, cudaStreamNonBlocking);
        cudaEventCreateWithFlags(&evFork, cudaEventDisableTiming);
        cudaEventCreateWithFlags(&evJoin, cudaEventDisableTiming);
    }

    cudaEventRecord(evFork, 0);
    cudaStreamWaitEvent(s2, evFork, 0);

    zero_deg_kernel<<<(NN + 255) / 256, 256, 0, s2>>>();                   // #0
    count_deg_kernel<<<(EE + 255) / 256, 256, 0, s2>>>(dst);               // #1

    prep_kernel<<<SPLIT_BLOCKS + T1_BLOCKS + T2_BLOCKS, 256>>>(x, W1, W2); // #2
    {
        dim3 grid(F1 / 128, (NN + 127) / 128);
        gemm_mma<128, 3, H0><<<grid, 512, SMEM1>>>((const __nv_bfloat16*)p_xhi,     // #3
                                                   (const __nv_bfloat16*)p_xlo,
                                                   (const __nv_bfloat16*)p_w1h,
                                                   (const __nv_bfloat16*)p_w1l,
                                                   (float*)p_feat1, al1, ar1,
                                                   (float*)p_el1, (float*)p_er1,
                                                   NN, F1, IN_DIM);
    }

    scan_kernel<<<1, 1024, 0, s2>>>();                                     // #4
    scatter_kernel<<<(EE + 255) / 256, 256, 0, s2>>>(src, dst);            // #5
    cudaEventRecord(evJoin, s2);

    cudaStreamWaitEvent(0, evJoin, 0);
    agg1_kernel<<<(NN * 32 + 255) / 256, 256>>>(b1);                       // #6

    {
        dim3 grid(1, (NN + 127) / 128);
        gemm_mma<64, 3, 1><<<grid, 512, SMEM2>>>((const __nv_bfloat16*)p_hhi,       // #7
                                                 (const __nv_bfloat16*)p_hlo,
                                                 (const __nv_bfloat16*)p_w2h,
                                                 (const __nv_bfloat16*)p_w2l,
                                                 (float*)p_feat2, al2, ar2,
                                                 (float*)p_el2, (float*)p_er2,
                                                 NN, OUTF, F1);
    }
    agg2_kernel<<<(NN * 32 + 255) / 256, 256>>>(b2, out);                  // #8
}

// round 12
// speedup vs baseline: 1.0705x; 1.0348x over previous
#include <cuda_runtime.h>
#include <cuda_bf16.h>
#include <cstdint>

#define NN      20000
#define EE      320000
#define IN_DIM  256
#define H0      4
#define D0      128
#define F1      512     // H0*D0
#define OUTF    64

// ---------------- device scratch (allocation-free contract) ----------------
__device__ float g_feat1[(size_t)NN * F1];
__device__ float g_feat2[(size_t)NN * OUTF];
__device__ __nv_bfloat16 g_xhi[(size_t)NN * IN_DIM];
__device__ __nv_bfloat16 g_xlo[(size_t)NN * IN_DIM];
__device__ __nv_bfloat16 g_hhi[(size_t)NN * F1];
__device__ __nv_bfloat16 g_hlo[(size_t)NN * F1];
__device__ __nv_bfloat16 g_w1t_hi[(size_t)F1 * IN_DIM];
__device__ __nv_bfloat16 g_w1t_lo[(size_t)F1 * IN_DIM];
__device__ __nv_bfloat16 g_w2t_hi[(size_t)OUTF * F1];
__device__ __nv_bfloat16 g_w2t_lo[(size_t)OUTF * F1];
__device__ float g_el1[NN * H0];
__device__ float g_er1[NN * H0];
__device__ float g_el2[NN];
__device__ float g_er2[NN];
__device__ int   g_deg[NN];
__device__ int   g_rowptr[NN + 1];
__device__ int   g_csr_src[EE];

// ---------------- helpers ----------------
__device__ __forceinline__ uint32_t smem_u32(const void* p) {
    uint32_t a;
    asm("{ .reg .u64 t; cvta.to.shared.u64 t, %1; cvt.u32.u64 %0, t; }" : "=r"(a) : "l"(p));
    return a;
}
__device__ __forceinline__ void ldsm_x4(uint32_t* r, uint32_t addr) {
    asm volatile("ldmatrix.sync.aligned.m8n8.x4.shared.b16 {%0,%1,%2,%3}, [%4];"
                 : "=r"(r[0]), "=r"(r[1]), "=r"(r[2]), "=r"(r[3]) : "r"(addr));
}
__device__ __forceinline__ void mma_bf16(float* c, const uint32_t* a, const uint32_t* b) {
    asm volatile(
        "mma.sync.aligned.m16n8k16.row.col.f32.bf16.bf16.f32 "
        "{%0,%1,%2,%3}, {%4,%5,%6,%7}, {%8,%9}, {%0,%1,%2,%3};"
        : "+f"(c[0]), "+f"(c[1]), "+f"(c[2]), "+f"(c[3])
        : "r"(a[0]), "r"(a[1]), "r"(a[2]), "r"(a[3]), "r"(b[0]), "r"(b[1]));
}
__device__ __forceinline__ uint32_t swz(int off) { return off ^ ((off >> 3) & 0x70); }
__device__ __forceinline__ float leaky(float e) { return fmaxf(e, 0.2f * e); }

// ---------------- CSR build ----------------
__global__ void zero_deg_kernel() {
    int i = blockIdx.x * blockDim.x + threadIdx.x;
    if (i < NN) g_deg[i] = 0;
}
__global__ void count_deg_kernel(const int* __restrict__ dst) {
    int i = blockIdx.x * blockDim.x + threadIdx.x;
    if (i < EE) atomicAdd(&g_deg[dst[i]], 1);
}
__global__ void scan_kernel() {
    __shared__ int partial[1024];
    const int CH = (NN + 1023) / 1024;
    int t = threadIdx.x;
    int base = t * CH;
    int s = 0;
    for (int i = 0; i < CH; i++) { int idx = base + i; if (idx < NN) s += g_deg[idx]; }
    partial[t] = s;
    __syncthreads();
    for (int off = 1; off < 1024; off <<= 1) {
        int v = (t >= off) ? partial[t - off] : 0;
        __syncthreads();
        partial[t] += v;
        __syncthreads();
    }
    int run = (t > 0) ? partial[t - 1] : 0;
    for (int i = 0; i < CH; i++) {
        int idx = base + i;
        if (idx < NN) { int d = g_deg[idx]; g_rowptr[idx] = run; run += d; g_deg[idx] = 0; }
    }
    if (t == 1023) g_rowptr[NN] = partial[1023];
}
__global__ void scatter_kernel(const int* __restrict__ src, const int* __restrict__ dst) {
    int i = blockIdx.x * blockDim.x + threadIdx.x;
    if (i >= EE) return;
    int d = dst[i];
    int pos = g_rowptr[d] + atomicAdd(&g_deg[d], 1);
    g_csr_src[pos] = src[i];
}

// ---------------- fused conversions + el/er zero ----------------
#define SPLIT_BLOCKS ((NN * IN_DIM / 4 + 255) / 256)
#define T1_BLOCKS    ((IN_DIM * F1 + 255) / 256)
#define T2_BLOCKS    ((F1 * OUTF + 255) / 256)
#define ZEL_COUNT    (NN * H0 * 2 + NN * 2)
#define ZEL_BLOCKS   ((ZEL_COUNT + 255) / 256)

__global__ void prep_kernel(const float* __restrict__ x, const float* __restrict__ W1,
                            const float* __restrict__ W2) {
    int b = blockIdx.x;
    int t = threadIdx.x;
    if (b < SPLIT_BLOCKS) {
        int i4 = (b * 256 + t) * 4;
        if (i4 >= NN * IN_DIM) return;
        float4 v = *(const float4*)(x + i4);
        __nv_bfloat16 h0 = __float2bfloat16(v.x), h1 = __float2bfloat16(v.y);
        __nv_bfloat16 h2 = __float2bfloat16(v.z), h3 = __float2bfloat16(v.w);
        __nv_bfloat16 l0 = __float2bfloat16(v.x - __bfloat162float(h0));
        __nv_bfloat16 l1 = __float2bfloat16(v.y - __bfloat162float(h1));
        __nv_bfloat16 l2 = __float2bfloat16(v.z - __bfloat162float(h2));
        __nv_bfloat16 l3 = __float2bfloat16(v.w - __bfloat162float(h3));
        __nv_bfloat162* ph = (__nv_bfloat162*)(g_xhi + i4);
        __nv_bfloat162* pl = (__nv_bfloat162*)(g_xlo + i4);
        ph[0] = __halves2bfloat162(h0, h1); ph[1] = __halves2bfloat162(h2, h3);
        pl[0] = __halves2bfloat162(l0, l1); pl[1] = __halves2bfloat162(l2, l3);
    } else if (b < SPLIT_BLOCKS + T1_BLOCKS) {
        int i = (b - SPLIT_BLOCKS) * 256 + t;
        if (i >= IN_DIM * F1) return;
        int k = i / F1, n = i - k * F1;
        float v = W1[i];
        __nv_bfloat16 h = __float2bfloat16(v);
        g_w1t_hi[(size_t)n * IN_DIM + k] = h;
        g_w1t_lo[(size_t)n * IN_DIM + k] = __float2bfloat16(v - __bfloat162float(h));
    } else if (b < SPLIT_BLOCKS + T1_BLOCKS + T2_BLOCKS) {
        int i = (b - SPLIT_BLOCKS - T1_BLOCKS) * 256 + t;
        if (i >= F1 * OUTF) return;
        int k = i / OUTF, n = i - k * OUTF;
        float v = W2[i];
        __nv_bfloat16 h = __float2bfloat16(v);
        g_w2t_hi[(size_t)n * F1 + k] = h;
        g_w2t_lo[(size_t)n * F1 + k] = __float2bfloat16(v - __bfloat162float(h));
    } else {
        int i = (b - SPLIT_BLOCKS - T1_BLOCKS - T2_BLOCKS) * 256 + t;
        if (i >= ZEL_COUNT) return;
        if (i < NN * H0) g_el1[i] = 0.f;
        else if (i < NN * H0 * 2) g_er1[i - NN * H0] = 0.f;
        else if (i < NN * H0 * 2 + NN) g_el2[i - NN * H0 * 2] = 0.f;
        else g_er2[i - NN * H0 * 2 - NN] = 0.f;
    }
}

// ---------------- bf16 mma.sync GEMM (512thr, 2 CTA/SM) + fused el/er ----------------
__device__ __forceinline__ void load_tile64_async(uint32_t sb, int smem_off,
    const __nv_bfloat16* __restrict__ g, int ldK, int kc,
    int row0, int rows, int rlim, int tid) {
    int units = rows * 8;
    for (int i = tid; i < units; i += 512) {
        int r = i >> 3, seg = i & 7;
        int gr = row0 + r;
        int ok = (gr < rlim);
        int sz = ok ? 16 : 0;
        const void* src = g + (size_t)(ok ? gr : 0) * ldK + kc + seg * 8;
        int off = r * 128 + seg * 16;
        off ^= (off >> 3) & 0x70;
        asm volatile("cp.async.cg.shared.global [%0], [%1], 16, %2;"
                     :: "r"(sb + smem_off + off), "l"(src), "r"(sz));
    }
}

// BM=128, BN=64, 2 stages (48KB each) -> ~99KB/CTA -> 2 CTA/SM.
// 16 warps: 4(m) x 4(n); warp tile 32 x 16; MT=2, NT=2.
template <int NSTAGE, int NH, int HEAD_DIV>
__global__ void __launch_bounds__(512, 2) gemm_mma(
    const __nv_bfloat16* __restrict__ Ahi, const __nv_bfloat16* __restrict__ Alo,
    const __nv_bfloat16* __restrict__ Bhi, const __nv_bfloat16* __restrict__ Blo,
    float* __restrict__ C,
    const float* __restrict__ alv, const float* __restrict__ arv,
    float* __restrict__ el, float* __restrict__ er,
    int M, int Nc, int K) {
    extern __shared__ char smem[];
    constexpr int BN = 64;
    constexpr int OFF_AH = 0;
    constexpr int OFF_AL = 16384;
    constexpr int OFF_BH = 32768;
    constexpr int OFF_BL = OFF_BH + BN * 128;
    constexpr int STAGE  = OFF_BL + BN * 128;            // 49152
    constexpr int WN = BN / 4;
    constexpr int NT = WN / 8;                           // 2
    constexpr int HEAD_COLS = BN * HEAD_DIV;

    const int tid = threadIdx.x;
    const int wid = tid >> 5;
    const int lane = tid & 31;
    const int wm = wid >> 2;
    const int wn = wid & 3;
    const int row0 = blockIdx.y * 128;
    const int col0 = blockIdx.x * BN;
    const int head = blockIdx.x / HEAD_DIV;
    const int hcol0 = col0 - head * HEAD_COLS;

    const uint32_t sb = smem_u32(smem);
    float* s_el = (float*)(smem + NSTAGE * STAGE);
    float* s_er = s_el + 128;

    if (tid < 128) { s_el[tid] = 0.f; s_er[tid] = 0.f; }

    float acc[2][NT][4];
#pragma unroll
    for (int i = 0; i < 2; i++)
#pragma unroll
        for (int j = 0; j < NT; j++)
#pragma unroll
            for (int q = 0; q < 4; q++) acc[i][j][q] = 0.f;

    const int a_r  = (lane & 15);
    const int a_kb = (lane >> 4) * 16;
    const int b_n  = (lane & 7) + ((lane >> 4) << 3);
    const int b_kb = ((lane >> 3) & 1) * 16;

    const int nchunks = K >> 6;

#pragma unroll
    for (int p = 0; p < NSTAGE - 1; p++) {
        if (p < nchunks) {
            uint32_t sp = sb + p * STAGE;
            int kc = p << 6;
            load_tile64_async(sp, OFF_AH, Ahi, K, kc, row0, 128, M, tid);
            load_tile64_async(sp, OFF_AL, Alo, K, kc, row0, 128, M, tid);
            load_tile64_async(sp, OFF_BH, Bhi, K, kc, col0, BN, Nc, tid);
            load_tile64_async(sp, OFF_BL, Blo, K, kc, col0, BN, Nc, tid);
            asm volatile("cp.async.commit_group;");
        }
    }

    for (int c = 0; c < nchunks; c++) {
        // CORRECT wait: outstanding groups at this point = min(NSTAGE-1, nchunks-c);
        // chunk c is the oldest -> wait until <= NSTAGE-2 remain (0 for 2-stage).
        if (c >= nchunks - (NSTAGE - 1))
            asm volatile("cp.async.wait_group 0;");
        else
            asm volatile("cp.async.wait_group %0;" :: "n"(NSTAGE - 2));
        __syncthreads();

        if (c + NSTAGE - 1 < nchunks) {
            int cn = c + NSTAGE - 1;
            uint32_t sn = sb + (cn % NSTAGE) * STAGE;
            int kc = cn << 6;
            load_tile64_async(sn, OFF_AH, Ahi, K, kc, row0, 128, M, tid);
            load_tile64_async(sn, OFF_AL, Alo, K, kc, row0, 128, M, tid);
            load_tile64_async(sn, OFF_BH, Bhi, K, kc, col0, BN, Nc, tid);
            load_tile64_async(sn, OFF_BL, Blo, K, kc, col0, BN, Nc, tid);
            asm volatile("cp.async.commit_group;");
        }

        const uint32_t sc = sb + (c % NSTAGE) * STAGE;
#pragma unroll
        for (int kk = 0; kk < 64; kk += 16) {
            uint32_t ah[2][4], al4[2][4];
#pragma unroll
            for (int mt = 0; mt < 2; mt++) {
                int r = wm * 32 + mt * 16 + a_r;
                int off = r * 128 + kk * 2 + a_kb;
                ldsm_x4(ah[mt], sc + OFF_AH + swz(off));
                ldsm_x4(al4[mt], sc + OFF_AL + swz(off));
            }
            uint32_t bh[NT][2], bl[NT][2];
            {
                int n = wn * WN + b_n;
                int off = n * 128 + kk * 2 + b_kb;
                uint32_t t4[4];
                ldsm_x4(t4, sc + OFF_BH + swz(off));
                bh[0][0] = t4[0]; bh[0][1] = t4[1];
                bh[1][0] = t4[2]; bh[1][1] = t4[3];
                ldsm_x4(t4, sc + OFF_BL + swz(off));
                bl[0][0] = t4[0]; bl[0][1] = t4[1];
                bl[1][0] = t4[2]; bl[1][1] = t4[3];
            }
#pragma unroll
            for (int mt = 0; mt < 2; mt++)
#pragma unroll
                for (int nt = 0; nt < NT; nt++) {
                    mma_bf16(acc[mt][nt], ah[mt], bh[nt]);
                    mma_bf16(acc[mt][nt], ah[mt], bl[nt]);
                    mma_bf16(acc[mt][nt], al4[mt], bh[nt]);
                }
        }
        __syncthreads();
    }

    float va[NT][2], vr[NT][2];
#pragma unroll
    for (int nt = 0; nt < NT; nt++) {
        int cL = hcol0 + wn * WN + nt * 8 + (lane & 3) * 2;
        va[nt][0] = alv[head * HEAD_COLS + cL];  va[nt][1] = alv[head * HEAD_COLS + cL + 1];
        vr[nt][0] = arv[head * HEAD_COLS + cL];  vr[nt][1] = arv[head * HEAD_COLS + cL + 1];
    }

#pragma unroll
    for (int mt = 0; mt < 2; mt++) {
        int rL0 = wm * 32 + mt * 16 + (lane >> 2);
        int m0 = row0 + rL0;
        float e0 = 0.f, r0 = 0.f, e1 = 0.f, r1 = 0.f;
#pragma unroll
        for (int nt = 0; nt < NT; nt++) {
            int n0 = col0 + wn * WN + nt * 8 + (lane & 3) * 2;
            if (m0 < M)
                *(float2*)(C + (size_t)m0 * Nc + n0) = make_float2(acc[mt][nt][0], acc[mt][nt][1]);
            if (m0 + 8 < M)
                *(float2*)(C + (size_t)(m0 + 8) * Nc + n0) = make_float2(acc[mt][nt][2], acc[mt][nt][3]);
            e0 += acc[mt][nt][0] * va[nt][0] + acc[mt][nt][1] * va[nt][1];
            r0 += acc[mt][nt][0] * vr[nt][0] + acc[mt][nt][1] * vr[nt][1];
            e1 += acc[mt][nt][2] * va[nt][0] + acc[mt][nt][3] * va[nt][1];
            r1 += acc[mt][nt][2] * vr[nt][0] + acc[mt][nt][3] * vr[nt][1];
        }
#pragma unroll
        for (int o = 1; o <= 2; o <<= 1) {
            e0 += __shfl_xor_sync(0xffffffffu, e0, o);
            r0 += __shfl_xor_sync(0xffffffffu, r0, o);
            e1 += __shfl_xor_sync(0xffffffffu, e1, o);
            r1 += __shfl_xor_sync(0xffffffffu, r1, o);
        }
        if ((lane & 3) == 0) {
            atomicAdd(&s_el[rL0], e0);
            atomicAdd(&s_er[rL0], r0);
            atomicAdd(&s_el[rL0 + 8], e1);
            atomicAdd(&s_er[rL0 + 8], r1);
        }
    }
    __syncthreads();
    if (tid < 128) {
        int node = row0 + tid;
        if (node < M) {
            if (HEAD_DIV == 1) {
                el[node * NH + head] = s_el[tid];
                er[node * NH + head] = s_er[tid];
            } else {
                atomicAdd(&el[node * NH + head], s_el[tid]);
                atomicAdd(&er[node * NH + head], s_er[tid]);
            }
        }
    }
}

// ---------------- layer-1 aggregation ----------------
__global__ void agg1_kernel(const float* __restrict__ b1) {
    int node = (blockIdx.x * blockDim.x + threadIdx.x) >> 5;
    int lane = threadIdx.x & 31;
    if (node >= NN) return;
    int beg = g_rowptr[node], end = g_rowptr[node + 1];

    int hh = lane & 3;
    float er_hh = g_er1[node * 4 + hh];

    float m = -INFINITY;
    for (int j = beg + (lane >> 2); j < end; j += 8) {
        int s = g_csr_src[j];
        m = fmaxf(m, leaky(g_el1[s * 4 + hh] + er_hh));
    }
#pragma unroll
    for (int o = 4; o < 32; o <<= 1) m = fmaxf(m, __shfl_xor_sync(0xffffffffu, m, o));

    float ssum = 0.f;
    for (int j = beg + (lane >> 2); j < end; j += 8) {
        int s = g_csr_src[j];
        ssum += __expf(leaky(g_el1[s * 4 + hh] + er_hh) - m);
    }
#pragma unroll
    for (int o = 4; o < 32; o <<= 1) ssum += __shfl_xor_sync(0xffffffffu, ssum, o);

    int myhead = lane >> 3;
    float m_h = __shfl_sync(0xffffffffu, m, myhead);
    float s_h = __shfl_sync(0xffffffffu, ssum, myhead);
    float er_mh = g_er1[node * 4 + myhead];
    float inv_s = 1.f / s_h;

    float acc[16];
#pragma unroll
    for (int q = 0; q < 16; q++) acc[q] = 0.f;

    int j = beg;
    for (; j + 4 <= end; j += 4) {
        int s0 = g_csr_src[j];
        int s1 = g_csr_src[j + 1];
        int s2 = g_csr_src[j + 2];
        int s3 = g_csr_src[j + 3];
        float a0 = __expf(leaky(g_el1[s0 * 4 + myhead] + er_mh) - m_h) * inv_s;
        float a1 = __expf(leaky(g_el1[s1 * 4 + myhead] + er_mh) - m_h) * inv_s;
        float a2 = __expf(leaky(g_el1[s2 * 4 + myhead] + er_mh) - m_h) * inv_s;
        float a3 = __expf(leaky(g_el1[s3 * 4 + myhead] + er_mh) - m_h) * inv_s;
        const float4* f0 = (const float4*)(g_feat1 + (size_t)s0 * F1 + lane * 16);
        const float4* f1 = (const float4*)(g_feat1 + (size_t)s1 * F1 + lane * 16);
        const float4* f2 = (const float4*)(g_feat1 + (size_t)s2 * F1 + lane * 16);
        const float4* f3 = (const float4*)(g_feat1 + (size_t)s3 * F1 + lane * 16);
#pragma unroll
        for (int q = 0; q < 4; q++) {
            float4 v0 = f0[q];
            float4 v1 = f1[q];
            float4 v2 = f2[q];
            float4 v3 = f3[q];
            acc[q * 4 + 0] += a0 * v0.x + a1 * v1.x + a2 * v2.x + a3 * v3.x;
            acc[q * 4 + 1] += a0 * v0.y + a1 * v1.y + a2 * v2.y + a3 * v3.y;
            acc[q * 4 + 2] += a0 * v0.z + a1 * v1.z + a2 * v2.z + a3 * v3.z;
            acc[q * 4 + 3] += a0 * v0.w + a1 * v1.w + a2 * v2.w + a3 * v3.w;
        }
    }
    for (; j < end; j++) {
        int s0 = g_csr_src[j];
        float a0 = __expf(leaky(g_el1[s0 * 4 + myhead] + er_mh) - m_h) * inv_s;
        const float4* f0 = (const float4*)(g_feat1 + (size_t)s0 * F1 + lane * 16);
#pragma unroll
        for (int q = 0; q < 4; q++) {
            float4 v0 = f0[q];
            acc[q * 4 + 0] += a0 * v0.x;
            acc[q * 4 + 1] += a0 * v0.y;
            acc[q * 4 + 2] += a0 * v0.z;
            acc[q * 4 + 3] += a0 * v0.w;
        }
    }

    size_t obase = (size_t)node * F1 + lane * 16;
#pragma unroll
    for (int q = 0; q < 4; q++) {
        float vv[4];
#pragma unroll
        for (int u = 0; u < 4; u++) {
            float v = acc[q * 4 + u] + b1[lane * 16 + q * 4 + u];
            vv[u] = v > 0.f ? v : expm1f(v);
        }
        __nv_bfloat16 h0 = __float2bfloat16(vv[0]), h1 = __float2bfloat16(vv[1]);
        __nv_bfloat16 h2 = __float2bfloat16(vv[2]), h3 = __float2bfloat16(vv[3]);
        __nv_bfloat16 l0 = __float2bfloat16(vv[0] - __bfloat162float(h0));
        __nv_bfloat16 l1 = __float2bfloat16(vv[1] - __bfloat162float(h1));
        __nv_bfloat16 l2 = __float2bfloat16(vv[2] - __bfloat162float(h2));
        __nv_bfloat16 l3 = __float2bfloat16(vv[3] - __bfloat162float(h3));
        __nv_bfloat162* ph = (__nv_bfloat162*)(g_hhi + obase + q * 4);
        __nv_bfloat162* pl = (__nv_bfloat162*)(g_hlo + obase + q * 4);
        ph[0] = __halves2bfloat162(h0, h1); ph[1] = __halves2bfloat162(h2, h3);
        pl[0] = __halves2bfloat162(l0, l1); pl[1] = __halves2bfloat162(l2, l3);
    }
}

// ---------------- layer-2 aggregation ----------------
__global__ void agg2_kernel(const float* __restrict__ b2, float* __restrict__ out) {
    int node = (blockIdx.x * blockDim.x + threadIdx.x) >> 5;
    int lane = threadIdx.x & 31;
    if (node >= NN) return;
    int beg = g_rowptr[node], end = g_rowptr[node + 1];

    float er_n = g_er2[node];

    float m = -INFINITY;
    for (int j = beg + lane; j < end; j += 32)
        m = fmaxf(m, leaky(g_el2[g_csr_src[j]] + er_n));
#pragma unroll
    for (int o = 16; o > 0; o >>= 1) m = fmaxf(m, __shfl_xor_sync(0xffffffffu, m, o));

    float ssum = 0.f;
    for (int j = beg + lane; j < end; j += 32)
        ssum += __expf(leaky(g_el2[g_csr_src[j]] + er_n) - m);
#pragma unroll
    for (int o = 16; o > 0; o >>= 1) ssum += __shfl_xor_sync(0xffffffffu, ssum, o);
    float inv_s = 1.f / ssum;

    float acc0 = 0.f, acc1 = 0.f;
    int j = beg;
    for (; j + 4 <= end; j += 4) {
        int s0 = g_csr_src[j];
        int s1 = g_csr_src[j + 1];
        int s2 = g_csr_src[j + 2];
        int s3 = g_csr_src[j + 3];
        float a0 = __expf(leaky(g_el2[s0] + er_n) - m) * inv_s;
        float a1 = __expf(leaky(g_el2[s1] + er_n) - m) * inv_s;
        float a2 = __expf(leaky(g_el2[s2] + er_n) - m) * inv_s;
        float a3 = __expf(leaky(g_el2[s3] + er_n) - m) * inv_s;
        float2 v0 = *(const float2*)(g_feat2 + (size_t)s0 * OUTF + lane * 2);
        float2 v1 = *(const float2*)(g_feat2 + (size_t)s1 * OUTF + lane * 2);
        float2 v2 = *(const float2*)(g_feat2 + (size_t)s2 * OUTF + lane * 2);
        float2 v3 = *(const float2*)(g_feat2 + (size_t)s3 * OUTF + lane * 2);
        acc0 += a0 * v0.x + a1 * v1.x + a2 * v2.x + a3 * v3.x;
        acc1 += a0 * v0.y + a1 * v1.y + a2 * v2.y + a3 * v3.y;
    }
    for (; j < end; j++) {
        int s0 = g_csr_src[j];
        float a0 = __expf(leaky(g_el2[s0] + er_n) - m) * inv_s;
        float2 v0 = *(const float2*)(g_feat2 + (size_t)s0 * OUTF + lane * 2);
        acc0 += a0 * v0.x;
        acc1 += a0 * v0.y;
    }
    float2 o2;
    o2.x = acc0 + b2[lane * 2 + 0];
    o2.y = acc1 + b2[lane * 2 + 1];
    *(float2*)(out + (size_t)node * OUTF + lane * 2) = o2;
}

// ---------------- host launch ----------------
extern "C" void kernel_launch(void* const* d_in, const int* in_sizes, int n_in,
                              void* d_out, int out_size) {
    const float* x   = (const float*)d_in[0];
    const int*   src = (const int*)d_in[1];
    const int*   dst = (const int*)d_in[2];
    const float* W1  = (const float*)d_in[3];
    const float* al1 = (const float*)d_in[4];
    const float* ar1 = (const float*)d_in[5];
    const float* b1  = (const float*)d_in[6];
    const float* W2  = (const float*)d_in[7];
    const float* al2 = (const float*)d_in[8];
    const float* ar2 = (const float*)d_in[9];
    const float* b2  = (const float*)d_in[10];
    float* out = (float*)d_out;

    void *p_feat1, *p_feat2, *p_el1, *p_er1, *p_el2, *p_er2;
    void *p_xhi, *p_xlo, *p_hhi, *p_hlo, *p_w1h, *p_w1l, *p_w2h, *p_w2l;
    cudaGetSymbolAddress(&p_feat1, g_feat1);
    cudaGetSymbolAddress(&p_feat2, g_feat2);
    cudaGetSymbolAddress(&p_el1, g_el1);
    cudaGetSymbolAddress(&p_er1, g_er1);
    cudaGetSymbolAddress(&p_el2, g_el2);
    cudaGetSymbolAddress(&p_er2, g_er2);
    cudaGetSymbolAddress(&p_xhi, g_xhi);
    cudaGetSymbolAddress(&p_xlo, g_xlo);
    cudaGetSymbolAddress(&p_hhi, g_hhi);
    cudaGetSymbolAddress(&p_hlo, g_hlo);
    cudaGetSymbolAddress(&p_w1h, g_w1t_hi);
    cudaGetSymbolAddress(&p_w1l, g_w1t_lo);
    cudaGetSymbolAddress(&p_w2h, g_w2t_hi);
    cudaGetSymbolAddress(&p_w2l, g_w2t_lo);

    const int SMEM = 2 * 49152 + 1024;   // 2 stages x 48KB + el/er buffers
    static bool attrs_set = false;
    if (!attrs_set) {
        cudaFuncSetAttribute(gemm_mma<2, H0, 2>, cudaFuncAttributeMaxDynamicSharedMemorySize, SMEM);
        cudaFuncSetAttribute(gemm_mma<2, 1, 1>,  cudaFuncAttributeMaxDynamicSharedMemorySize, SMEM);
        attrs_set = true;
    }

    static cudaStream_t s2 = nullptr;
    static cudaEvent_t evFork = nullptr, evJoin = nullptr;
    if (!s2) {
        cudaStreamCreateWithFlags(&s2, cudaStreamNonBlocking);
        cudaEventCreateWithFlags(&evFork, cudaEventDisableTiming);
        cudaEventCreateWithFlags(&evJoin, cudaEventDisableTiming);
    }

    cudaEventRecord(evFork, 0);
    cudaStreamWaitEvent(s2, evFork, 0);

    zero_deg_kernel<<<(NN + 255) / 256, 256, 0, s2>>>();                   // #0
    count_deg_kernel<<<(EE + 255) / 256, 256, 0, s2>>>(dst);               // #1

    prep_kernel<<<SPLIT_BLOCKS + T1_BLOCKS + T2_BLOCKS + ZEL_BLOCKS, 256>>>(x, W1, W2); // #2
    {
        dim3 grid(F1 / 64, (NN + 127) / 128);
        gemm_mma<2, H0, 2><<<grid, 512, SMEM>>>((const __nv_bfloat16*)p_xhi,        // #3
                                                (const __nv_bfloat16*)p_xlo,
                                                (const __nv_bfloat16*)p_w1h,
                                                (const __nv_bfloat16*)p_w1l,
                                                (float*)p_feat1, al1, ar1,
                                                (float*)p_el1, (float*)p_er1,
                                                NN, F1, IN_DIM);
    }

    scan_kernel<<<1, 1024, 0, s2>>>();                                     // #4
    scatter_kernel<<<(EE + 255) / 256, 256, 0, s2>>>(src, dst);            // #5
    cudaEventRecord(evJoin, s2);

    cudaStreamWaitEvent(0, evJoin, 0);
    agg1_kernel<<<(NN * 32 + 255) / 256, 256>>>(b1);                       // #6

    {
        dim3 grid(1, (NN + 127) / 128);
        gemm_mma<2, 1, 1><<<grid, 512, SMEM>>>((const __nv_bfloat16*)p_hhi,         // #7
                                               (const __nv_bfloat16*)p_hlo,
                                               (const __nv_bfloat16*)p_w2h,
                                               (const __nv_bfloat16*)p_w2l,
                                               (float*)p_feat2, al2, ar2,
                                               (float*)p_el2, (float*)p_er2,
                                               NN, OUTF, F1);
    }
    agg2_kernel<<<(NN * 32 + 255) / 256, 256>>>(b2, out);                  // #8
}

// round 13
// speedup vs baseline: 1.0812x; 1.0100x over previous
#include <cuda_runtime.h>
#include <cuda_bf16.h>
#include <cstdint>

#define NN      20000
#define EE      320000
#define IN_DIM  256
#define H0      4
#define D0      128
#define F1      512     // H0*D0
#define OUTF    64

// ---------------- device scratch (allocation-free contract) ----------------
__device__ float g_feat1[(size_t)NN * F1];
__device__ float g_feat2[(size_t)NN * OUTF];
__device__ __nv_bfloat16 g_xhi[(size_t)NN * IN_DIM];
__device__ __nv_bfloat16 g_xlo[(size_t)NN * IN_DIM];
__device__ __nv_bfloat16 g_hhi[(size_t)NN * F1];
__device__ __nv_bfloat16 g_hlo[(size_t)NN * F1];
__device__ __nv_bfloat16 g_w1t_hi[(size_t)F1 * IN_DIM];
__device__ __nv_bfloat16 g_w1t_lo[(size_t)F1 * IN_DIM];
__device__ __nv_bfloat16 g_w2t_hi[(size_t)OUTF * F1];
__device__ __nv_bfloat16 g_w2t_lo[(size_t)OUTF * F1];
__device__ float g_el1[NN * H0];
__device__ float g_er1[NN * H0];
__device__ float g_el2[NN];
__device__ float g_er2[NN];
__device__ int   g_deg[NN];
__device__ int   g_rowptr[NN + 1];
__device__ int   g_csr_src[EE];

// ---------------- helpers ----------------
__device__ __forceinline__ uint32_t smem_u32(const void* p) {
    uint32_t a;
    asm("{ .reg .u64 t; cvta.to.shared.u64 t, %1; cvt.u32.u64 %0, t; }" : "=r"(a) : "l"(p));
    return a;
}
__device__ __forceinline__ void ldsm_x4(uint32_t* r, uint32_t addr) {
    asm volatile("ldmatrix.sync.aligned.m8n8.x4.shared.b16 {%0,%1,%2,%3}, [%4];"
                 : "=r"(r[0]), "=r"(r[1]), "=r"(r[2]), "=r"(r[3]) : "r"(addr));
}
__device__ __forceinline__ void mma_bf16(float* c, const uint32_t* a, const uint32_t* b) {
    asm volatile(
        "mma.sync.aligned.m16n8k16.row.col.f32.bf16.bf16.f32 "
        "{%0,%1,%2,%3}, {%4,%5,%6,%7}, {%8,%9}, {%0,%1,%2,%3};"
        : "+f"(c[0]), "+f"(c[1]), "+f"(c[2]), "+f"(c[3])
        : "r"(a[0]), "r"(a[1]), "r"(a[2]), "r"(a[3]), "r"(b[0]), "r"(b[1]));
}
__device__ __forceinline__ uint32_t swz(int off) { return off ^ ((off >> 3) & 0x70); }
__device__ __forceinline__ float leaky(float e) { return fmaxf(e, 0.2f * e); }

// ---------------- CSR build ----------------
__global__ void zero_deg_kernel() {
    int i = blockIdx.x * blockDim.x + threadIdx.x;
    if (i < NN) g_deg[i] = 0;
}
__global__ void count_deg_kernel(const int* __restrict__ dst) {
    int i = blockIdx.x * blockDim.x + threadIdx.x;
    if (i < EE) atomicAdd(&g_deg[dst[i]], 1);
}
__global__ void scan_kernel() {
    __shared__ int partial[1024];
    const int CH = (NN + 1023) / 1024;
    int t = threadIdx.x;
    int base = t * CH;
    int s = 0;
    for (int i = 0; i < CH; i++) { int idx = base + i; if (idx < NN) s += g_deg[idx]; }
    partial[t] = s;
    __syncthreads();
    for (int off = 1; off < 1024; off <<= 1) {
        int v = (t >= off) ? partial[t - off] : 0;
        __syncthreads();
        partial[t] += v;
        __syncthreads();
    }
    int run = (t > 0) ? partial[t - 1] : 0;
    for (int i = 0; i < CH; i++) {
        int idx = base + i;
        if (idx < NN) { int d = g_deg[idx]; g_rowptr[idx] = run; run += d; g_deg[idx] = 0; }
    }
    if (t == 1023) g_rowptr[NN] = partial[1023];
}
__global__ void scatter_kernel(const int* __restrict__ src, const int* __restrict__ dst) {
    int i = blockIdx.x * blockDim.x + threadIdx.x;
    if (i >= EE) return;
    int d = dst[i];
    int pos = g_rowptr[d] + atomicAdd(&g_deg[d], 1);
    g_csr_src[pos] = src[i];
}

// ---------------- fused conversions + el/er zero ----------------
#define SPLIT_BLOCKS ((NN * IN_DIM / 4 + 255) / 256)
#define T1_BLOCKS    ((IN_DIM * F1 + 255) / 256)
#define T2_BLOCKS    ((F1 * OUTF + 255) / 256)
#define ZEL_COUNT    (NN * H0 * 2 + NN * 2)
#define ZEL_BLOCKS   ((ZEL_COUNT + 255) / 256)

__global__ void prep_kernel(const float* __restrict__ x, const float* __restrict__ W1,
                            const float* __restrict__ W2) {
    int b = blockIdx.x;
    int t = threadIdx.x;
    if (b < SPLIT_BLOCKS) {
        int i4 = (b * 256 + t) * 4;
        if (i4 >= NN * IN_DIM) return;
        float4 v = *(const float4*)(x + i4);
        __nv_bfloat16 h0 = __float2bfloat16(v.x), h1 = __float2bfloat16(v.y);
        __nv_bfloat16 h2 = __float2bfloat16(v.z), h3 = __float2bfloat16(v.w);
        __nv_bfloat16 l0 = __float2bfloat16(v.x - __bfloat162float(h0));
        __nv_bfloat16 l1 = __float2bfloat16(v.y - __bfloat162float(h1));
        __nv_bfloat16 l2 = __float2bfloat16(v.z - __bfloat162float(h2));
        __nv_bfloat16 l3 = __float2bfloat16(v.w - __bfloat162float(h3));
        __nv_bfloat162* ph = (__nv_bfloat162*)(g_xhi + i4);
        __nv_bfloat162* pl = (__nv_bfloat162*)(g_xlo + i4);
        ph[0] = __halves2bfloat162(h0, h1); ph[1] = __halves2bfloat162(h2, h3);
        pl[0] = __halves2bfloat162(l0, l1); pl[1] = __halves2bfloat162(l2, l3);
    } else if (b < SPLIT_BLOCKS + T1_BLOCKS) {
        int i = (b - SPLIT_BLOCKS) * 256 + t;
        if (i >= IN_DIM * F1) return;
        int k = i / F1, n = i - k * F1;
        float v = W1[i];
        __nv_bfloat16 h = __float2bfloat16(v);
        g_w1t_hi[(size_t)n * IN_DIM + k] = h;
        g_w1t_lo[(size_t)n * IN_DIM + k] = __float2bfloat16(v - __bfloat162float(h));
    } else if (b < SPLIT_BLOCKS + T1_BLOCKS + T2_BLOCKS) {
        int i = (b - SPLIT_BLOCKS - T1_BLOCKS) * 256 + t;
        if (i >= F1 * OUTF) return;
        int k = i / OUTF, n = i - k * OUTF;
        float v = W2[i];
        __nv_bfloat16 h = __float2bfloat16(v);
        g_w2t_hi[(size_t)n * F1 + k] = h;
        g_w2t_lo[(size_t)n * F1 + k] = __float2bfloat16(v - __bfloat162float(h));
    } else {
        int i = (b - SPLIT_BLOCKS - T1_BLOCKS - T2_BLOCKS) * 256 + t;
        if (i >= ZEL_COUNT) return;
        if (i < NN * H0) g_el1[i] = 0.f;
        else if (i < NN * H0 * 2) g_er1[i - NN * H0] = 0.f;
        else if (i < NN * H0 * 2 + NN) g_el2[i - NN * H0 * 2] = 0.f;
        else g_er2[i - NN * H0 * 2 - NN] = 0.f;
    }
}

// ---------------- bf16 mma.sync GEMM (256thr, 2 CTA/SM, warp 32x32) + fused el/er ----------------
__device__ __forceinline__ void load_tile64_async(uint32_t sb, int smem_off,
    const __nv_bfloat16* __restrict__ g, int ldK, int kc,
    int row0, int rows, int rlim, int tid) {
    int units = rows * 8;
    for (int i = tid; i < units; i += 256) {
        int r = i >> 3, seg = i & 7;
        int gr = row0 + r;
        int ok = (gr < rlim);
        int sz = ok ? 16 : 0;
        const void* src = g + (size_t)(ok ? gr : 0) * ldK + kc + seg * 8;
        int off = r * 128 + seg * 16;
        off ^= (off >> 3) & 0x70;
        asm volatile("cp.async.cg.shared.global [%0], [%1], 16, %2;"
                     :: "r"(sb + smem_off + off), "l"(src), "r"(sz));
    }
}

// BM=128, BN=64, 2 stages (48KB) -> ~97KB/CTA -> 2 CTA/SM.
// 8 warps: 4(m) x 2(n); warp tile 32 x 32; MT=2, NT=4. 3.0 MMA per LDSM.x4.
template <int NSTAGE, int NH, int HEAD_DIV>
__global__ void __launch_bounds__(256, 2) gemm_mma(
    const __nv_bfloat16* __restrict__ Ahi, const __nv_bfloat16* __restrict__ Alo,
    const __nv_bfloat16* __restrict__ Bhi, const __nv_bfloat16* __restrict__ Blo,
    float* __restrict__ C,
    const float* __restrict__ alv, const float* __restrict__ arv,
    float* __restrict__ el, float* __restrict__ er,
    int M, int Nc, int K) {
    extern __shared__ char smem[];
    constexpr int BN = 64;
    constexpr int OFF_AH = 0;
    constexpr int OFF_AL = 16384;
    constexpr int OFF_BH = 32768;
    constexpr int OFF_BL = OFF_BH + BN * 128;
    constexpr int STAGE  = OFF_BL + BN * 128;            // 49152
    constexpr int WN = 32;                               // warp n-extent
    constexpr int NT = 4;
    constexpr int HEAD_COLS = BN * HEAD_DIV;

    const int tid = threadIdx.x;
    const int wid = tid >> 5;
    const int lane = tid & 31;
    const int wm = wid >> 1;      // 0..3
    const int wn = wid & 1;       // 0..1
    const int row0 = blockIdx.y * 128;
    const int col0 = blockIdx.x * BN;
    const int head = blockIdx.x / HEAD_DIV;
    const int hcol0 = col0 - head * HEAD_COLS;

    const uint32_t sb = smem_u32(smem);
    float* s_el = (float*)(smem + NSTAGE * STAGE);
    float* s_er = s_el + 128;

    if (tid < 128) { s_el[tid] = 0.f; s_er[tid] = 0.f; }

    float acc[2][NT][4];
#pragma unroll
    for (int i = 0; i < 2; i++)
#pragma unroll
        for (int j = 0; j < NT; j++)
#pragma unroll
            for (int q = 0; q < 4; q++) acc[i][j][q] = 0.f;

    const int a_r  = (lane & 15);
    const int a_kb = (lane >> 4) * 16;
    const int b_n  = (lane & 7) + ((lane >> 4) << 3);
    const int b_kb = ((lane >> 3) & 1) * 16;

    const int nchunks = K >> 6;

#pragma unroll
    for (int p = 0; p < NSTAGE - 1; p++) {
        if (p < nchunks) {
            uint32_t sp = sb + p * STAGE;
            int kc = p << 6;
            load_tile64_async(sp, OFF_AH, Ahi, K, kc, row0, 128, M, tid);
            load_tile64_async(sp, OFF_AL, Alo, K, kc, row0, 128, M, tid);
            load_tile64_async(sp, OFF_BH, Bhi, K, kc, col0, BN, Nc, tid);
            load_tile64_async(sp, OFF_BL, Blo, K, kc, col0, BN, Nc, tid);
            asm volatile("cp.async.commit_group;");
        }
    }

    for (int c = 0; c < nchunks; c++) {
        if (c >= nchunks - (NSTAGE - 1))
            asm volatile("cp.async.wait_group 0;");
        else
            asm volatile("cp.async.wait_group %0;" :: "n"(NSTAGE - 2));
        __syncthreads();

        if (c + NSTAGE - 1 < nchunks) {
            int cn = c + NSTAGE - 1;
            uint32_t sn = sb + (cn % NSTAGE) * STAGE;
            int kc = cn << 6;
            load_tile64_async(sn, OFF_AH, Ahi, K, kc, row0, 128, M, tid);
            load_tile64_async(sn, OFF_AL, Alo, K, kc, row0, 128, M, tid);
            load_tile64_async(sn, OFF_BH, Bhi, K, kc, col0, BN, Nc, tid);
            load_tile64_async(sn, OFF_BL, Blo, K, kc, col0, BN, Nc, tid);
            asm volatile("cp.async.commit_group;");
        }

        const uint32_t sc = sb + (c % NSTAGE) * STAGE;
#pragma unroll
        for (int kk = 0; kk < 64; kk += 16) {
            uint32_t ah[2][4], al4[2][4];
#pragma unroll
            for (int mt = 0; mt < 2; mt++) {
                int r = wm * 32 + mt * 16 + a_r;
                int off = r * 128 + kk * 2 + a_kb;
                ldsm_x4(ah[mt], sc + OFF_AH + swz(off));
                ldsm_x4(al4[mt], sc + OFF_AL + swz(off));
            }
            uint32_t bh[NT][2], bl[NT][2];
#pragma unroll
            for (int bt = 0; bt < NT / 2; bt++) {
                int n = wn * WN + bt * 16 + b_n;
                int off = n * 128 + kk * 2 + b_kb;
                uint32_t t4[4];
                ldsm_x4(t4, sc + OFF_BH + swz(off));
                bh[2 * bt][0] = t4[0]; bh[2 * bt][1] = t4[1];
                bh[2 * bt + 1][0] = t4[2]; bh[2 * bt + 1][1] = t4[3];
                ldsm_x4(t4, sc + OFF_BL + swz(off));
                bl[2 * bt][0] = t4[0]; bl[2 * bt][1] = t4[1];
                bl[2 * bt + 1][0] = t4[2]; bl[2 * bt + 1][1] = t4[3];
            }
#pragma unroll
            for (int mt = 0; mt < 2; mt++)
#pragma unroll
                for (int nt = 0; nt < NT; nt++) {
                    mma_bf16(acc[mt][nt], ah[mt], bh[nt]);
                    mma_bf16(acc[mt][nt], ah[mt], bl[nt]);
                    mma_bf16(acc[mt][nt], al4[mt], bh[nt]);
                }
        }
        __syncthreads();
    }

    float va[NT][2], vr[NT][2];
#pragma unroll
    for (int nt = 0; nt < NT; nt++) {
        int cL = hcol0 + wn * WN + nt * 8 + (lane & 3) * 2;
        va[nt][0] = alv[head * HEAD_COLS + cL];  va[nt][1] = alv[head * HEAD_COLS + cL + 1];
        vr[nt][0] = arv[head * HEAD_COLS + cL];  vr[nt][1] = arv[head * HEAD_COLS + cL + 1];
    }

#pragma unroll
    for (int mt = 0; mt < 2; mt++) {
        int rL0 = wm * 32 + mt * 16 + (lane >> 2);
        int m0 = row0 + rL0;
        float e0 = 0.f, r0 = 0.f, e1 = 0.f, r1 = 0.f;
#pragma unroll
        for (int nt = 0; nt < NT; nt++) {
            int n0 = col0 + wn * WN + nt * 8 + (lane & 3) * 2;
            if (m0 < M)
                *(float2*)(C + (size_t)m0 * Nc + n0) = make_float2(acc[mt][nt][0], acc[mt][nt][1]);
            if (m0 + 8 < M)
                *(float2*)(C + (size_t)(m0 + 8) * Nc + n0) = make_float2(acc[mt][nt][2], acc[mt][nt][3]);
            e0 += acc[mt][nt][0] * va[nt][0] + acc[mt][nt][1] * va[nt][1];
            r0 += acc[mt][nt][0] * vr[nt][0] + acc[mt][nt][1] * vr[nt][1];
            e1 += acc[mt][nt][2] * va[nt][0] + acc[mt][nt][3] * va[nt][1];
            r1 += acc[mt][nt][2] * vr[nt][0] + acc[mt][nt][3] * vr[nt][1];
        }
#pragma unroll
        for (int o = 1; o <= 2; o <<= 1) {
            e0 += __shfl_xor_sync(0xffffffffu, e0, o);
            r0 += __shfl_xor_sync(0xffffffffu, r0, o);
            e1 += __shfl_xor_sync(0xffffffffu, e1, o);
            r1 += __shfl_xor_sync(0xffffffffu, r1, o);
        }
        if ((lane & 3) == 0) {
            atomicAdd(&s_el[rL0], e0);
            atomicAdd(&s_er[rL0], r0);
            atomicAdd(&s_el[rL0 + 8], e1);
            atomicAdd(&s_er[rL0 + 8], r1);
        }
    }
    __syncthreads();
    if (tid < 128) {
        int node = row0 + tid;
        if (node < M) {
            if (HEAD_DIV == 1) {
                el[node * NH + head] = s_el[tid];
                er[node * NH + head] = s_er[tid];
            } else {
                atomicAdd(&el[node * NH + head], s_el[tid]);
                atomicAdd(&er[node * NH + head], s_er[tid]);
            }
        }
    }
}

// ---------------- layer-1 aggregation ----------------
__global__ void agg1_kernel(const float* __restrict__ b1) {
    int node = (blockIdx.x * blockDim.x + threadIdx.x) >> 5;
    int lane = threadIdx.x & 31;
    if (node >= NN) return;
    int beg = g_rowptr[node], end = g_rowptr[node + 1];

    int hh = lane & 3;
    float er_hh = g_er1[node * 4 + hh];

    float m = -INFINITY;
    for (int j = beg + (lane >> 2); j < end; j += 8) {
        int s = g_csr_src[j];
        m = fmaxf(m, leaky(g_el1[s * 4 + hh] + er_hh));
    }
#pragma unroll
    for (int o = 4; o < 32; o <<= 1) m = fmaxf(m, __shfl_xor_sync(0xffffffffu, m, o));

    float ssum = 0.f;
    for (int j = beg + (lane >> 2); j < end; j += 8) {
        int s = g_csr_src[j];
        ssum += __expf(leaky(g_el1[s * 4 + hh] + er_hh) - m);
    }
#pragma unroll
    for (int o = 4; o < 32; o <<= 1) ssum += __shfl_xor_sync(0xffffffffu, ssum, o);

    int myhead = lane >> 3;
    float m_h = __shfl_sync(0xffffffffu, m, myhead);
    float s_h = __shfl_sync(0xffffffffu, ssum, myhead);
    float er_mh = g_er1[node * 4 + myhead];
    float inv_s = 1.f / s_h;

    float acc[16];
#pragma unroll
    for (int q = 0; q < 16; q++) acc[q] = 0.f;

    int j = beg;
    for (; j + 4 <= end; j += 4) {
        int s0 = g_csr_src[j];
        int s1 = g_csr_src[j + 1];
        int s2 = g_csr_src[j + 2];
        int s3 = g_csr_src[j + 3];
        float a0 = __expf(leaky(g_el1[s0 * 4 + myhead] + er_mh) - m_h) * inv_s;
        float a1 = __expf(leaky(g_el1[s1 * 4 + myhead] + er_mh) - m_h) * inv_s;
        float a2 = __expf(leaky(g_el1[s2 * 4 + myhead] + er_mh) - m_h) * inv_s;
        float a3 = __expf(leaky(g_el1[s3 * 4 + myhead] + er_mh) - m_h) * inv_s;
        const float4* f0 = (const float4*)(g_feat1 + (size_t)s0 * F1 + lane * 16);
        const float4* f1 = (const float4*)(g_feat1 + (size_t)s1 * F1 + lane * 16);
        const float4* f2 = (const float4*)(g_feat1 + (size_t)s2 * F1 + lane * 16);
        const float4* f3 = (const float4*)(g_feat1 + (size_t)s3 * F1 + lane * 16);
#pragma unroll
        for (int q = 0; q < 4; q++) {
            float4 v0 = f0[q];
            float4 v1 = f1[q];
            float4 v2 = f2[q];
            float4 v3 = f3[q];
            acc[q * 4 + 0] += a0 * v0.x + a1 * v1.x + a2 * v2.x + a3 * v3.x;
            acc[q * 4 + 1] += a0 * v0.y + a1 * v1.y + a2 * v2.y + a3 * v3.y;
            acc[q * 4 + 2] += a0 * v0.z + a1 * v1.z + a2 * v2.z + a3 * v3.z;
            acc[q * 4 + 3] += a0 * v0.w + a1 * v1.w + a2 * v2.w + a3 * v3.w;
        }
    }
    for (; j < end; j++) {
        int s0 = g_csr_src[j];
        float a0 = __expf(leaky(g_el1[s0 * 4 + myhead] + er_mh) - m_h) * inv_s;
        const float4* f0 = (const float4*)(g_feat1 + (size_t)s0 * F1 + lane * 16);
#pragma unroll
        for (int q = 0; q < 4; q++) {
            float4 v0 = f0[q];
            acc[q * 4 + 0] += a0 * v0.x;
            acc[q * 4 + 1] += a0 * v0.y;
            acc[q * 4 + 2] += a0 * v0.z;
            acc[q * 4 + 3] += a0 * v0.w;
        }
    }

    size_t obase = (size_t)node * F1 + lane * 16;
#pragma unroll
    for (int q = 0; q < 4; q++) {
        float vv[4];
#pragma unroll
        for (int u = 0; u < 4; u++) {
            float v = acc[q * 4 + u] + b1[lane * 16 + q * 4 + u];
            vv[u] = v > 0.f ? v : expm1f(v);
        }
        __nv_bfloat16 h0 = __float2bfloat16(vv[0]), h1 = __float2bfloat16(vv[1]);
        __nv_bfloat16 h2 = __float2bfloat16(vv[2]), h3 = __float2bfloat16(vv[3]);
        __nv_bfloat16 l0 = __float2bfloat16(vv[0] - __bfloat162float(h0));
        __nv_bfloat16 l1 = __float2bfloat16(vv[1] - __bfloat162float(h1));
        __nv_bfloat16 l2 = __float2bfloat16(vv[2] - __bfloat162float(h2));
        __nv_bfloat16 l3 = __float2bfloat16(vv[3] - __bfloat162float(h3));
        __nv_bfloat162* ph = (__nv_bfloat162*)(g_hhi + obase + q * 4);
        __nv_bfloat162* pl = (__nv_bfloat162*)(g_hlo + obase + q * 4);
        ph[0] = __halves2bfloat162(h0, h1); ph[1] = __halves2bfloat162(h2, h3);
        pl[0] = __halves2bfloat162(l0, l1); pl[1] = __halves2bfloat162(l2, l3);
    }
}

// ---------------- layer-2 aggregation ----------------
__global__ void agg2_kernel(const float* __restrict__ b2, float* __restrict__ out) {
    int node = (blockIdx.x * blockDim.x + threadIdx.x) >> 5;
    int lane = threadIdx.x & 31;
    if (node >= NN) return;
    int beg = g_rowptr[node], end = g_rowptr[node + 1];

    float er_n = g_er2[node];

    float m = -INFINITY;
    for (int j = beg + lane; j < end; j += 32)
        m = fmaxf(m, leaky(g_el2[g_csr_src[j]] + er_n));
#pragma unroll
    for (int o = 16; o > 0; o >>= 1) m = fmaxf(m, __shfl_xor_sync(0xffffffffu, m, o));

    float ssum = 0.f;
    for (int j = beg + lane; j < end; j += 32)
        ssum += __expf(leaky(g_el2[g_csr_src[j]] + er_n) - m);
#pragma unroll
    for (int o = 16; o > 0; o >>= 1) ssum += __shfl_xor_sync(0xffffffffu, ssum, o);
    float inv_s = 1.f / ssum;

    float acc0 = 0.f, acc1 = 0.f;
    int j = beg;
    for (; j + 4 <= end; j += 4) {
        int s0 = g_csr_src[j];
        int s1 = g_csr_src[j + 1];
        int s2 = g_csr_src[j + 2];
        int s3 = g_csr_src[j + 3];
        float a0 = __expf(leaky(g_el2[s0] + er_n) - m) * inv_s;
        float a1 = __expf(leaky(g_el2[s1] + er_n) - m) * inv_s;
        float a2 = __expf(leaky(g_el2[s2] + er_n) - m) * inv_s;
        float a3 = __expf(leaky(g_el2[s3] + er_n) - m) * inv_s;
        float2 v0 = *(const float2*)(g_feat2 + (size_t)s0 * OUTF + lane * 2);
        float2 v1 = *(const float2*)(g_feat2 + (size_t)s1 * OUTF + lane * 2);
        float2 v2 = *(const float2*)(g_feat2 + (size_t)s2 * OUTF + lane * 2);
        float2 v3 = *(const float2*)(g_feat2 + (size_t)s3 * OUTF + lane * 2);
        acc0 += a0 * v0.x + a1 * v1.x + a2 * v2.x + a3 * v3.x;
        acc1 += a0 * v0.y + a1 * v1.y + a2 * v2.y + a3 * v3.y;
    }
    for (; j < end; j++) {
        int s0 = g_csr_src[j];
        float a0 = __expf(leaky(g_el2[s0] + er_n) - m) * inv_s;
        float2 v0 = *(const float2*)(g_feat2 + (size_t)s0 * OUTF + lane * 2);
        acc0 += a0 * v0.x;
        acc1 += a0 * v0.y;
    }
    float2 o2;
    o2.x = acc0 + b2[lane * 2 + 0];
    o2.y = acc1 + b2[lane * 2 + 1];
    *(float2*)(out + (size_t)node * OUTF + lane * 2) = o2;
}

// ---------------- host launch ----------------
extern "C" void kernel_launch(void* const* d_in, const int* in_sizes, int n_in,
                              void* d_out, int out_size) {
    const float* x   = (const float*)d_in[0];
    const int*   src = (const int*)d_in[1];
    const int*   dst = (const int*)d_in[2];
    const float* W1  = (const float*)d_in[3];
    const float* al1 = (const float*)d_in[4];
    const float* ar1 = (const float*)d_in[5];
    const float* b1  = (const float*)d_in[6];
    const float* W2  = (const float*)d_in[7];
    const float* al2 = (const float*)d_in[8];
    const float* ar2 = (const float*)d_in[9];
    const float* b2  = (const float*)d_in[10];
    float* out = (float*)d_out;

    void *p_feat1, *p_feat2, *p_el1, *p_er1, *p_el2, *p_er2;
    void *p_xhi, *p_xlo, *p_hhi, *p_hlo, *p_w1h, *p_w1l, *p_w2h, *p_w2l;
    cudaGetSymbolAddress(&p_feat1, g_feat1);
    cudaGetSymbolAddress(&p_feat2, g_feat2);
    cudaGetSymbolAddress(&p_el1, g_el1);
    cudaGetSymbolAddress(&p_er1, g_er1);
    cudaGetSymbolAddress(&p_el2, g_el2);
    cudaGetSymbolAddress(&p_er2, g_er2);
    cudaGetSymbolAddress(&p_xhi, g_xhi);
    cudaGetSymbolAddress(&p_xlo, g_xlo);
    cudaGetSymbolAddress(&p_hhi, g_hhi);
    cudaGetSymbolAddress(&p_hlo, g_hlo);
    cudaGetSymbolAddress(&p_w1h, g_w1t_hi);
    cudaGetSymbolAddress(&p_w1l, g_w1t_lo);
    cudaGetSymbolAddress(&p_w2h, g_w2t_hi);
    cudaGetSymbolAddress(&p_w2l, g_w2t_lo);

    const int SMEM = 2 * 49152 + 1024;
    static bool attrs_set = false;
    if (!attrs_set) {
        cudaFuncSetAttribute(gemm_mma<2, H0, 2>, cudaFuncAttributeMaxDynamicSharedMemorySize, SMEM);
        cudaFuncSetAttribute(gemm_mma<2, 1, 1>,  cudaFuncAttributeMaxDynamicSharedMemorySize, SMEM);
        attrs_set = true;
    }

    static cudaStream_t s2 = nullptr;
    static cudaEvent_t evFork = nullptr, evJoin = nullptr;
    if (!s2) {
        cudaStreamCreateWithFlags(&s2, cudaStreamNonBlocking);
        cudaEventCreateWithFlags(&evFork, cudaEventDisableTiming);
        cudaEventCreateWithFlags(&evJoin, cudaEventDisableTiming);
    }

    cudaEventRecord(evFork, 0);
    cudaStreamWaitEvent(s2, evFork, 0);

    zero_deg_kernel<<<(NN + 255) / 256, 256, 0, s2>>>();                   // #0
    count_deg_kernel<<<(EE + 255) / 256, 256, 0, s2>>>(dst);               // #1

    prep_kernel<<<SPLIT_BLOCKS + T1_BLOCKS + T2_BLOCKS + ZEL_BLOCKS, 256>>>(x, W1, W2); // #2
    {
        dim3 grid(F1 / 64, (NN + 127) / 128);
        gemm_mma<2, H0, 2><<<grid, 256, SMEM>>>((const __nv_bfloat16*)p_xhi,        // #3
                                                (const __nv_bfloat16*)p_xlo,
                                                (const __nv_bfloat16*)p_w1h,
                                                (const __nv_bfloat16*)p_w1l,
                                                (float*)p_feat1, al1, ar1,
                                                (float*)p_el1, (float*)p_er1,
                                                NN, F1, IN_DIM);
    }

    scan_kernel<<<1, 1024, 0, s2>>>();                                     // #4
    scatter_kernel<<<(EE + 255) / 256, 256, 0, s2>>>(src, dst);            // #5
    cudaEventRecord(evJoin, s2);

    cudaStreamWaitEvent(0, evJoin, 0);
    agg1_kernel<<<(NN * 32 + 255) / 256, 256>>>(b1);                       // #6

    {
        dim3 grid(1, (NN + 127) / 128);
        gemm_mma<2, 1, 1><<<grid, 256, SMEM>>>((const __nv_bfloat16*)p_hhi,         // #7
                                               (const __nv_bfloat16*)p_hlo,
                                               (const __nv_bfloat16*)p_w2h,
                                               (const __nv_bfloat16*)p_w2l,
                                               (float*)p_feat2, al2, ar2,
                                               (float*)p_el2, (float*)p_er2,
                                               NN, OUTF, F1);
    }
    agg2_kernel<<<(NN * 32 + 255) / 256, 256>>>(b2, out);                  // #8
}

// round 15
// speedup vs baseline: 1.4559x; 1.3466x over previous
#include <cuda_runtime.h>
#include <cuda_bf16.h>
#include <cuda_fp16.h>
#include <cstdint>

#define NN      20000
#define EE      320000
#define IN_DIM  256
#define H0      4
#define D0      128
#define F1      512     // H0*D0
#define OUTF    64

// ---------------- device scratch (allocation-free contract) ----------------
__device__ __half g_feat1h[(size_t)NN * F1];   // layer-1 proj, fp16 (only consumer: agg1)
__device__ float g_feat2[(size_t)NN * OUTF];
__device__ __nv_bfloat16 g_xhi[(size_t)NN * IN_DIM];
__device__ __nv_bfloat16 g_xlo[(size_t)NN * IN_DIM];
__device__ __nv_bfloat16 g_hhi[(size_t)NN * F1];
__device__ __nv_bfloat16 g_hlo[(size_t)NN * F1];
__device__ __nv_bfloat16 g_w1t_hi[(size_t)F1 * IN_DIM];
__device__ __nv_bfloat16 g_w1t_lo[(size_t)F1 * IN_DIM];
__device__ __nv_bfloat16 g_w2t_hi[(size_t)OUTF * F1];
__device__ __nv_bfloat16 g_w2t_lo[(size_t)OUTF * F1];
__device__ float g_el1[NN * H0];
__device__ float g_er1[NN * H0];
__device__ float g_el2[NN];
__device__ float g_er2[NN];
__device__ int   g_deg[NN];
__device__ int   g_rowptr[NN + 1];
__device__ int   g_csr_src[EE];

// ---------------- helpers ----------------
__device__ __forceinline__ uint32_t smem_u32(const void* p) {
    uint32_t a;
    asm("{ .reg .u64 t; cvta.to.shared.u64 t, %1; cvt.u32.u64 %0, t; }" : "=r"(a) : "l"(p));
    return a;
}
__device__ __forceinline__ void ldsm_x4(uint32_t* r, uint32_t addr) {
    asm volatile("ldmatrix.sync.aligned.m8n8.x4.shared.b16 {%0,%1,%2,%3}, [%4];"
                 : "=r"(r[0]), "=r"(r[1]), "=r"(r[2]), "=r"(r[3]) : "r"(addr));
}
__device__ __forceinline__ void mma_bf16(float* c, const uint32_t* a, const uint32_t* b) {
    asm volatile(
        "mma.sync.aligned.m16n8k16.row.col.f32.bf16.bf16.f32 "
        "{%0,%1,%2,%3}, {%4,%5,%6,%7}, {%8,%9}, {%0,%1,%2,%3};"
        : "+f"(c[0]), "+f"(c[1]), "+f"(c[2]), "+f"(c[3])
        : "r"(a[0]), "r"(a[1]), "r"(a[2]), "r"(a[3]), "r"(b[0]), "r"(b[1]));
}
__device__ __forceinline__ uint32_t swz(int off) { return off ^ ((off >> 3) & 0x70); }
__device__ __forceinline__ float leaky(float e) { return fmaxf(e, 0.2f * e); }

// ---------------- CSR build ----------------
__global__ void zero_deg_kernel() {
    int i = blockIdx.x * blockDim.x + threadIdx.x;
    if (i < NN) g_deg[i] = 0;
}
__global__ void count_deg_kernel(const int* __restrict__ dst) {
    int i = blockIdx.x * blockDim.x + threadIdx.x;
    if (i < EE) atomicAdd(&g_deg[dst[i]], 1);
}
__global__ void scan_kernel() {
    __shared__ int partial[1024];
    const int CH = (NN + 1023) / 1024;
    int t = threadIdx.x;
    int base = t * CH;
    int s = 0;
    for (int i = 0; i < CH; i++) { int idx = base + i; if (idx < NN) s += g_deg[idx]; }
    partial[t] = s;
    __syncthreads();
    for (int off = 1; off < 1024; off <<= 1) {
        int v = (t >= off) ? partial[t - off] : 0;
        __syncthreads();
        partial[t] += v;
        __syncthreads();
    }
    int run = (t > 0) ? partial[t - 1] : 0;
    for (int i = 0; i < CH; i++) {
        int idx = base + i;
        if (idx < NN) { int d = g_deg[idx]; g_rowptr[idx] = run; run += d; g_deg[idx] = 0; }
    }
    if (t == 1023) g_rowptr[NN] = partial[1023];
}
__global__ void scatter_kernel(const int* __restrict__ src, const int* __restrict__ dst) {
    int i = blockIdx.x * blockDim.x + threadIdx.x;
    if (i >= EE) return;
    int d = dst[i];
    int pos = g_rowptr[d] + atomicAdd(&g_deg[d], 1);
    g_csr_src[pos] = src[i];
}

// ---------------- fused conversions + el/er zero ----------------
#define SPLIT_BLOCKS ((NN * IN_DIM / 4 + 255) / 256)
#define T1_BLOCKS    ((IN_DIM * F1 + 255) / 256)
#define T2_BLOCKS    ((F1 * OUTF + 255) / 256)
#define ZEL_COUNT    (NN * H0 * 2 + NN * 2)
#define ZEL_BLOCKS   ((ZEL_COUNT + 255) / 256)

__global__ void prep_kernel(const float* __restrict__ x, const float* __restrict__ W1,
                            const float* __restrict__ W2) {
    int b = blockIdx.x;
    int t = threadIdx.x;
    if (b < SPLIT_BLOCKS) {
        int i4 = (b * 256 + t) * 4;
        if (i4 >= NN * IN_DIM) return;
        float4 v = *(const float4*)(x + i4);
        __nv_bfloat16 h0 = __float2bfloat16(v.x), h1 = __float2bfloat16(v.y);
        __nv_bfloat16 h2 = __float2bfloat16(v.z), h3 = __float2bfloat16(v.w);
        __nv_bfloat16 l0 = __float2bfloat16(v.x - __bfloat162float(h0));
        __nv_bfloat16 l1 = __float2bfloat16(v.y - __bfloat162float(h1));
        __nv_bfloat16 l2 = __float2bfloat16(v.z - __bfloat162float(h2));
        __nv_bfloat16 l3 = __float2bfloat16(v.w - __bfloat162float(h3));
        __nv_bfloat162* ph = (__nv_bfloat162*)(g_xhi + i4);
        __nv_bfloat162* pl = (__nv_bfloat162*)(g_xlo + i4);
        ph[0] = __halves2bfloat162(h0, h1); ph[1] = __halves2bfloat162(h2, h3);
        pl[0] = __halves2bfloat162(l0, l1); pl[1] = __halves2bfloat162(l2, l3);
    } else if (b < SPLIT_BLOCKS + T1_BLOCKS) {
        int i = (b - SPLIT_BLOCKS) * 256 + t;
        if (i >= IN_DIM * F1) return;
        int k = i / F1, n = i - k * F1;
        float v = W1[i];
        __nv_bfloat16 h = __float2bfloat16(v);
        g_w1t_hi[(size_t)n * IN_DIM + k] = h;
        g_w1t_lo[(size_t)n * IN_DIM + k] = __float2bfloat16(v - __bfloat162float(h));
    } else if (b < SPLIT_BLOCKS + T1_BLOCKS + T2_BLOCKS) {
        int i = (b - SPLIT_BLOCKS - T1_BLOCKS) * 256 + t;
        if (i >= F1 * OUTF) return;
        int k = i / OUTF, n = i - k * OUTF;
        float v = W2[i];
        __nv_bfloat16 h = __float2bfloat16(v);
        g_w2t_hi[(size_t)n * F1 + k] = h;
        g_w2t_lo[(size_t)n * F1 + k] = __float2bfloat16(v - __bfloat162float(h));
    } else {
        int i = (b - SPLIT_BLOCKS - T1_BLOCKS - T2_BLOCKS) * 256 + t;
        if (i >= ZEL_COUNT) return;
        if (i < NN * H0) g_el1[i] = 0.f;
        else if (i < NN * H0 * 2) g_er1[i - NN * H0] = 0.f;
        else if (i < NN * H0 * 2 + NN) g_el2[i - NN * H0 * 2] = 0.f;
        else g_er2[i - NN * H0 * 2 - NN] = 0.f;
    }
}

// ---------------- bf16 mma.sync GEMM (256thr, 2 CTA/SM, warp 32x32) + fused el/er ----------------
__device__ __forceinline__ void load_tile64_async(uint32_t sb, int smem_off,
    const __nv_bfloat16* __restrict__ g, int ldK, int kc,
    int row0, int rows, int rlim, int tid) {
    int units = rows * 8;
    for (int i = tid; i < units; i += 256) {
        int r = i >> 3, seg = i & 7;
        int gr = row0 + r;
        int ok = (gr < rlim);
        int sz = ok ? 16 : 0;
        const void* src = g + (size_t)(ok ? gr : 0) * ldK + kc + seg * 8;
        int off = r * 128 + seg * 16;
        off ^= (off >> 3) & 0x70;
        asm volatile("cp.async.cg.shared.global [%0], [%1], 16, %2;"
                     :: "r"(sb + smem_off + off), "l"(src), "r"(sz));
    }
}

// BM=128, BN=64, 2 stages (48KB) -> ~97KB/CTA -> 2 CTA/SM.
// 8 warps: 4(m) x 2(n); warp tile 32x32; MT=2, NT=4. FP16C: write C as fp16.
template <int NSTAGE, int NH, int HEAD_DIV, bool FP16C>
__global__ void __launch_bounds__(256, 2) gemm_mma(
    const __nv_bfloat16* __restrict__ Ahi, const __nv_bfloat16* __restrict__ Alo,
    const __nv_bfloat16* __restrict__ Bhi, const __nv_bfloat16* __restrict__ Blo,
    void* __restrict__ Cv,
    const float* __restrict__ alv, const float* __restrict__ arv,
    float* __restrict__ el, float* __restrict__ er,
    int M, int Nc, int K) {
    extern __shared__ char smem[];
    constexpr int BN = 64;
    constexpr int OFF_AH = 0;
    constexpr int OFF_AL = 16384;
    constexpr int OFF_BH = 32768;
    constexpr int OFF_BL = OFF_BH + BN * 128;
    constexpr int STAGE  = OFF_BL + BN * 128;
    constexpr int WN = 32;
    constexpr int NT = 4;
    constexpr int HEAD_COLS = BN * HEAD_DIV;

    const int tid = threadIdx.x;
    const int wid = tid >> 5;
    const int lane = tid & 31;
    const int wm = wid >> 1;
    const int wn = wid & 1;
    const int row0 = blockIdx.y * 128;
    const int col0 = blockIdx.x * BN;
    const int head = blockIdx.x / HEAD_DIV;
    const int hcol0 = col0 - head * HEAD_COLS;

    const uint32_t sb = smem_u32(smem);
    float* s_el = (float*)(smem + NSTAGE * STAGE);
    float* s_er = s_el + 128;

    if (tid < 128) { s_el[tid] = 0.f; s_er[tid] = 0.f; }

    float acc[2][NT][4];
#pragma unroll
    for (int i = 0; i < 2; i++)
#pragma unroll
        for (int j = 0; j < NT; j++)
#pragma unroll
            for (int q = 0; q < 4; q++) acc[i][j][q] = 0.f;

    const int a_r  = (lane & 15);
    const int a_kb = (lane >> 4) * 16;
    const int b_n  = (lane & 7) + ((lane >> 4) << 3);
    const int b_kb = ((lane >> 3) & 1) * 16;

    const int nchunks = K >> 6;

#pragma unroll
    for (int p = 0; p < NSTAGE - 1; p++) {
        if (p < nchunks) {
            uint32_t sp = sb + p * STAGE;
            int kc = p << 6;
            load_tile64_async(sp, OFF_AH, Ahi, K, kc, row0, 128, M, tid);
            load_tile64_async(sp, OFF_AL, Alo, K, kc, row0, 128, M, tid);
            load_tile64_async(sp, OFF_BH, Bhi, K, kc, col0, BN, Nc, tid);
            load_tile64_async(sp, OFF_BL, Blo, K, kc, col0, BN, Nc, tid);
            asm volatile("cp.async.commit_group;");
        }
    }

    for (int c = 0; c < nchunks; c++) {
        if (c >= nchunks - (NSTAGE - 1))
            asm volatile("cp.async.wait_group 0;");
        else
            asm volatile("cp.async.wait_group %0;" :: "n"(NSTAGE - 2));
        __syncthreads();

        if (c + NSTAGE - 1 < nchunks) {
            int cn = c + NSTAGE - 1;
            uint32_t sn = sb + (cn % NSTAGE) * STAGE;
            int kc = cn << 6;
            load_tile64_async(sn, OFF_AH, Ahi, K, kc, row0, 128, M, tid);
            load_tile64_async(sn, OFF_AL, Alo, K, kc, row0, 128, M, tid);
            load_tile64_async(sn, OFF_BH, Bhi, K, kc, col0, BN, Nc, tid);
            load_tile64_async(sn, OFF_BL, Blo, K, kc, col0, BN, Nc, tid);
            asm volatile("cp.async.commit_group;");
        }

        const uint32_t sc = sb + (c % NSTAGE) * STAGE;
#pragma unroll
        for (int kk = 0; kk < 64; kk += 16) {
            uint32_t ah[2][4], al4[2][4];
#pragma unroll
            for (int mt = 0; mt < 2; mt++) {
                int r = wm * 32 + mt * 16 + a_r;
                int off = r * 128 + kk * 2 + a_kb;
                ldsm_x4(ah[mt], sc + OFF_AH + swz(off));
                ldsm_x4(al4[mt], sc + OFF_AL + swz(off));
            }
            uint32_t bh[NT][2], bl[NT][2];
#pragma unroll
            for (int bt = 0; bt < NT / 2; bt++) {
                int n = wn * WN + bt * 16 + b_n;
                int off = n * 128 + kk * 2 + b_kb;
                uint32_t t4[4];
                ldsm_x4(t4, sc + OFF_BH + swz(off));
                bh[2 * bt][0] = t4[0]; bh[2 * bt][1] = t4[1];
                bh[2 * bt + 1][0] = t4[2]; bh[2 * bt + 1][1] = t4[3];
                ldsm_x4(t4, sc + OFF_BL + swz(off));
                bl[2 * bt][0] = t4[0]; bl[2 * bt][1] = t4[1];
                bl[2 * bt + 1][0] = t4[2]; bl[2 * bt + 1][1] = t4[3];
            }
#pragma unroll
            for (int mt = 0; mt < 2; mt++)
#pragma unroll
                for (int nt = 0; nt < NT; nt++) {
                    mma_bf16(acc[mt][nt], ah[mt], bh[nt]);
                    mma_bf16(acc[mt][nt], ah[mt], bl[nt]);
                    mma_bf16(acc[mt][nt], al4[mt], bh[nt]);
                }
        }
        __syncthreads();
    }

    float va[NT][2], vr[NT][2];
#pragma unroll
    for (int nt = 0; nt < NT; nt++) {
        int cL = hcol0 + wn * WN + nt * 8 + (lane & 3) * 2;
        va[nt][0] = alv[head * HEAD_COLS + cL];  va[nt][1] = alv[head * HEAD_COLS + cL + 1];
        vr[nt][0] = arv[head * HEAD_COLS + cL];  vr[nt][1] = arv[head * HEAD_COLS + cL + 1];
    }

#pragma unroll
    for (int mt = 0; mt < 2; mt++) {
        int rL0 = wm * 32 + mt * 16 + (lane >> 2);
        int m0 = row0 + rL0;
        float e0 = 0.f, r0 = 0.f, e1 = 0.f, r1 = 0.f;
#pragma unroll
        for (int nt = 0; nt < NT; nt++) {
            int n0 = col0 + wn * WN + nt * 8 + (lane & 3) * 2;
            if (FP16C) {
                __half* Ch = (__half*)Cv;
                if (m0 < M)
                    *(__half2*)(Ch + (size_t)m0 * Nc + n0) =
                        __floats2half2_rn(acc[mt][nt][0], acc[mt][nt][1]);
                if (m0 + 8 < M)
                    *(__half2*)(Ch + (size_t)(m0 + 8) * Nc + n0) =
                        __floats2half2_rn(acc[mt][nt][2], acc[mt][nt][3]);
            } else {
                float* Cf = (float*)Cv;
                if (m0 < M)
                    *(float2*)(Cf + (size_t)m0 * Nc + n0) = make_float2(acc[mt][nt][0], acc[mt][nt][1]);
                if (m0 + 8 < M)
                    *(float2*)(Cf + (size_t)(m0 + 8) * Nc + n0) = make_float2(acc[mt][nt][2], acc[mt][nt][3]);
            }
            e0 += acc[mt][nt][0] * va[nt][0] + acc[mt][nt][1] * va[nt][1];
            r0 += acc[mt][nt][0] * vr[nt][0] + acc[mt][nt][1] * vr[nt][1];
            e1 += acc[mt][nt][2] * va[nt][0] + acc[mt][nt][3] * va[nt][1];
            r1 += acc[mt][nt][2] * vr[nt][0] + acc[mt][nt][3] * vr[nt][1];
        }
#pragma unroll
        for (int o = 1; o <= 2; o <<= 1) {
            e0 += __shfl_xor_sync(0xffffffffu, e0, o);
            r0 += __shfl_xor_sync(0xffffffffu, r0, o);
            e1 += __shfl_xor_sync(0xffffffffu, e1, o);
            r1 += __shfl_xor_sync(0xffffffffu, r1, o);
        }
        if ((lane & 3) == 0) {
            atomicAdd(&s_el[rL0], e0);
            atomicAdd(&s_er[rL0], r0);
            atomicAdd(&s_el[rL0 + 8], e1);
            atomicAdd(&s_er[rL0 + 8], r1);
        }
    }
    __syncthreads();
    if (tid < 128) {
        int node = row0 + tid;
        if (node < M) {
            if (HEAD_DIV == 1) {
                el[node * NH + head] = s_el[tid];
                er[node * NH + head] = s_er[tid];
            } else {
                atomicAdd(&el[node * NH + head], s_el[tid]);
                atomicAdd(&er[node * NH + head], s_er[tid]);
            }
        }
    }
}

// ---------------- layer-1 aggregation (fp16 feat gather) ----------------
__device__ __forceinline__ void acc_h16_edge(float* acc, const __half* fbase, float a) {
    const uint4* fp = (const uint4*)fbase;    // 16 half = 32 bytes = 2 x uint4
    uint4 u0 = fp[0];
    uint4 u1 = fp[1];
    const uint32_t w[8] = {u0.x, u0.y, u0.z, u0.w, u1.x, u1.y, u1.z, u1.w};
#pragma unroll
    for (int q = 0; q < 8; q++) {
        float2 v = __half22float2(*(const __half2*)&w[q]);
        acc[q * 2 + 0] += a * v.x;
        acc[q * 2 + 1] += a * v.y;
    }
}

__global__ void agg1_kernel(const float* __restrict__ b1) {
    int node = (blockIdx.x * blockDim.x + threadIdx.x) >> 5;
    int lane = threadIdx.x & 31;
    if (node >= NN) return;
    int beg = g_rowptr[node], end = g_rowptr[node + 1];

    int hh = lane & 3;
    float er_hh = g_er1[node * 4 + hh];

    float m = -INFINITY;
    for (int j = beg + (lane >> 2); j < end; j += 8) {
        int s = g_csr_src[j];
        m = fmaxf(m, leaky(g_el1[s * 4 + hh] + er_hh));
    }
#pragma unroll
    for (int o = 4; o < 32; o <<= 1) m = fmaxf(m, __shfl_xor_sync(0xffffffffu, m, o));

    float ssum = 0.f;
    for (int j = beg + (lane >> 2); j < end; j += 8) {
        int s = g_csr_src[j];
        ssum += __expf(leaky(g_el1[s * 4 + hh] + er_hh) - m);
    }
#pragma unroll
    for (int o = 4; o < 32; o <<= 1) ssum += __shfl_xor_sync(0xffffffffu, ssum, o);

    int myhead = lane >> 3;
    float m_h = __shfl_sync(0xffffffffu, m, myhead);
    float s_h = __shfl_sync(0xffffffffu, ssum, myhead);
    float er_mh = g_er1[node * 4 + myhead];
    float inv_s = 1.f / s_h;

    float acc[16];
#pragma unroll
    for (int q = 0; q < 16; q++) acc[q] = 0.f;

    int j = beg;
    for (; j + 4 <= end; j += 4) {
        int s0 = g_csr_src[j];
        int s1 = g_csr_src[j + 1];
        int s2 = g_csr_src[j + 2];
        int s3 = g_csr_src[j + 3];
        float a0 = __expf(leaky(g_el1[s0 * 4 + myhead] + er_mh) - m_h) * inv_s;
        float a1 = __expf(leaky(g_el1[s1 * 4 + myhead] + er_mh) - m_h) * inv_s;
        float a2 = __expf(leaky(g_el1[s2 * 4 + myhead] + er_mh) - m_h) * inv_s;
        float a3 = __expf(leaky(g_el1[s3 * 4 + myhead] + er_mh) - m_h) * inv_s;
        acc_h16_edge(acc, g_feat1h + (size_t)s0 * F1 + lane * 16, a0);
        acc_h16_edge(acc, g_feat1h + (size_t)s1 * F1 + lane * 16, a1);
        acc_h16_edge(acc, g_feat1h + (size_t)s2 * F1 + lane * 16, a2);
        acc_h16_edge(acc, g_feat1h + (size_t)s3 * F1 + lane * 16, a3);
    }
    for (; j < end; j++) {
        int s0 = g_csr_src[j];
        float a0 = __expf(leaky(g_el1[s0 * 4 + myhead] + er_mh) - m_h) * inv_s;
        acc_h16_edge(acc, g_feat1h + (size_t)s0 * F1 + lane * 16, a0);
    }

    size_t obase = (size_t)node * F1 + lane * 16;
#pragma unroll
    for (int q = 0; q < 4; q++) {
        float vv[4];
#pragma unroll
        for (int u = 0; u < 4; u++) {
            float v = acc[q * 4 + u] + b1[lane * 16 + q * 4 + u];
            vv[u] = v > 0.f ? v : expm1f(v);
        }
        __nv_bfloat16 h0 = __float2bfloat16(vv[0]), h1 = __float2bfloat16(vv[1]);
        __nv_bfloat16 h2 = __float2bfloat16(vv[2]), h3 = __float2bfloat16(vv[3]);
        __nv_bfloat16 l0 = __float2bfloat16(vv[0] - __bfloat162float(h0));
        __nv_bfloat16 l1 = __float2bfloat16(vv[1] - __bfloat162float(h1));
        __nv_bfloat16 l2 = __float2bfloat16(vv[2] - __bfloat162float(h2));
        __nv_bfloat16 l3 = __float2bfloat16(vv[3] - __bfloat162float(h3));
        __nv_bfloat162* ph = (__nv_bfloat162*)(g_hhi + obase + q * 4);
        __nv_bfloat162* pl = (__nv_bfloat162*)(g_hlo + obase + q * 4);
        ph[0] = __halves2bfloat162(h0, h1); ph[1] = __halves2bfloat162(h2, h3);
        pl[0] = __halves2bfloat162(l0, l1); pl[1] = __halves2bfloat162(l2, l3);
    }
}

// ---------------- layer-2 aggregation ----------------
__global__ void agg2_kernel(const float* __restrict__ b2, float* __restrict__ out) {
    int node = (blockIdx.x * blockDim.x + threadIdx.x) >> 5;
    int lane = threadIdx.x & 31;
    if (node >= NN) return;
    int beg = g_rowptr[node], end = g_rowptr[node + 1];

    float er_n = g_er2[node];

    float m = -INFINITY;
    for (int j = beg + lane; j < end; j += 32)
        m = fmaxf(m, leaky(g_el2[g_csr_src[j]] + er_n));
#pragma unroll
    for (int o = 16; o > 0; o >>= 1) m = fmaxf(m, __shfl_xor_sync(0xffffffffu, m, o));

    float ssum = 0.f;
    for (int j = beg + lane; j < end; j += 32)
        ssum += __expf(leaky(g_el2[g_csr_src[j]] + er_n) - m);
#pragma unroll
    for (int o = 16; o > 0; o >>= 1) ssum += __shfl_xor_sync(0xffffffffu, ssum, o);
    float inv_s = 1.f / ssum;

    float acc0 = 0.f, acc1 = 0.f;
    int j = beg;
    for (; j + 4 <= end; j += 4) {
        int s0 = g_csr_src[j];
        int s1 = g_csr_src[j + 1];
        int s2 = g_csr_src[j + 2];
        int s3 = g_csr_src[j + 3];
        float a0 = __expf(leaky(g_el2[s0] + er_n) - m) * inv_s;
        float a1 = __expf(leaky(g_el2[s1] + er_n) - m) * inv_s;
        float a2 = __expf(leaky(g_el2[s2] + er_n) - m) * inv_s;
        float a3 = __expf(leaky(g_el2[s3] + er_n) - m) * inv_s;
        float2 v0 = *(const float2*)(g_feat2 + (size_t)s0 * OUTF + lane * 2);
        float2 v1 = *(const float2*)(g_feat2 + (size_t)s1 * OUTF + lane * 2);
        float2 v2 = *(const float2*)(g_feat2 + (size_t)s2 * OUTF + lane * 2);
        float2 v3 = *(const float2*)(g_feat2 + (size_t)s3 * OUTF + lane * 2);
        acc0 += a0 * v0.x + a1 * v1.x + a2 * v2.x + a3 * v3.x;
        acc1 += a0 * v0.y + a1 * v1.y + a2 * v2.y + a3 * v3.y;
    }
    for (; j < end; j++) {
        int s0 = g_csr_src[j];
        float a0 = __expf(leaky(g_el2[s0] + er_n) - m) * inv_s;
        float2 v0 = *(const float2*)(g_feat2 + (size_t)s0 * OUTF + lane * 2);
        acc0 += a0 * v0.x;
        acc1 += a0 * v0.y;
    }
    float2 o2;
    o2.x = acc0 + b2[lane * 2 + 0];
    o2.y = acc1 + b2[lane * 2 + 1];
    *(float2*)(out + (size_t)node * OUTF + lane * 2) = o2;
}

// ---------------- host launch ----------------
extern "C" void kernel_launch(void* const* d_in, const int* in_sizes, int n_in,
                              void* d_out, int out_size) {
    const float* x   = (const float*)d_in[0];
    const int*   src = (const int*)d_in[1];
    const int*   dst = (const int*)d_in[2];
    const float* W1  = (const float*)d_in[3];
    const float* al1 = (const float*)d_in[4];
    const float* ar1 = (const float*)d_in[5];
    const float* b1  = (const float*)d_in[6];
    const float* W2  = (const float*)d_in[7];
    const float* al2 = (const float*)d_in[8];
    const float* ar2 = (const float*)d_in[9];
    const float* b2  = (const float*)d_in[10];
    float* out = (float*)d_out;

    void *p_feat1h, *p_feat2, *p_el1, *p_er1, *p_el2, *p_er2;
    void *p_xhi, *p_xlo, *p_hhi, *p_hlo, *p_w1h, *p_w1l, *p_w2h, *p_w2l;
    cudaGetSymbolAddress(&p_feat1h, g_feat1h);
    cudaGetSymbolAddress(&p_feat2, g_feat2);
    cudaGetSymbolAddress(&p_el1, g_el1);
    cudaGetSymbolAddress(&p_er1, g_er1);
    cudaGetSymbolAddress(&p_el2, g_el2);
    cudaGetSymbolAddress(&p_er2, g_er2);
    cudaGetSymbolAddress(&p_xhi, g_xhi);
    cudaGetSymbolAddress(&p_xlo, g_xlo);
    cudaGetSymbolAddress(&p_hhi, g_hhi);
    cudaGetSymbolAddress(&p_hlo, g_hlo);
    cudaGetSymbolAddress(&p_w1h, g_w1t_hi);
    cudaGetSymbolAddress(&p_w1l, g_w1t_lo);
    cudaGetSymbolAddress(&p_w2h, g_w2t_hi);
    cudaGetSymbolAddress(&p_w2l, g_w2t_lo);

    const int SMEM = 2 * 49152 + 1024;
    static bool attrs_set = false;
    if (!attrs_set) {
        cudaFuncSetAttribute((const void*)gemm_mma<2, H0, 2, true>,
                             cudaFuncAttributeMaxDynamicSharedMemorySize, SMEM);
        cudaFuncSetAttribute((const void*)gemm_mma<2, 1, 1, false>,
                             cudaFuncAttributeMaxDynamicSharedMemorySize, SMEM);
        attrs_set = true;
    }

    static cudaStream_t s2 = nullptr;
    static cudaEvent_t evFork = nullptr, evJoin = nullptr;
    if (!s2) {
        cudaStreamCreateWithFlags(&s2, cudaStreamNonBlocking);
        cudaEventCreateWithFlags(&evFork, cudaEventDisableTiming);
        cudaEventCreateWithFlags(&evJoin, cudaEventDisableTiming);
    }

    cudaEventRecord(evFork, 0);
    cudaStreamWaitEvent(s2, evFork, 0);

    zero_deg_kernel<<<(NN + 255) / 256, 256, 0, s2>>>();                   // #0
    count_deg_kernel<<<(EE + 255) / 256, 256, 0, s2>>>(dst);               // #1

    prep_kernel<<<SPLIT_BLOCKS + T1_BLOCKS + T2_BLOCKS + ZEL_BLOCKS, 256>>>(x, W1, W2); // #2
    {
        dim3 grid(F1 / 64, (NN + 127) / 128);
        gemm_mma<2, H0, 2, true><<<grid, 256, SMEM>>>((const __nv_bfloat16*)p_xhi,  // #3
                                                      (const __nv_bfloat16*)p_xlo,
                                                      (const __nv_bfloat16*)p_w1h,
                                                      (const __nv_bfloat16*)p_w1l,
                                                      p_feat1h, al1, ar1,
                                                      (float*)p_el1, (float*)p_er1,
                                                      NN, F1, IN_DIM);
    }

    scan_kernel<<<1, 1024, 0, s2>>>();                                     // #4
    scatter_kernel<<<(EE + 255) / 256, 256, 0, s2>>>(src, dst);            // #5
    cudaEventRecord(evJoin, s2);

    cudaStreamWaitEvent(0, evJoin, 0);
    agg1_kernel<<<(NN * 32 + 255) / 256, 256>>>(b1);                       // #6

    {
        dim3 grid(1, (NN + 127) / 128);
        gemm_mma<2, 1, 1, false><<<grid, 256, SMEM>>>((const __nv_bfloat16*)p_hhi,  // #7
                                                      (const __nv_bfloat16*)p_hlo,
                                                      (const __nv_bfloat16*)p_w2h,
                                                      (const __nv_bfloat16*)p_w2l,
                                                      p_feat2, al2, ar2,
                                                      (float*)p_el2, (float*)p_er2,
                                                      NN, OUTF, F1);
    }
    agg2_kernel<<<(NN * 32 + 255) / 256, 256>>>(b2, out);                  // #8
}

// round 17
// speedup vs baseline: 1.4580x; 1.0014x over previous
#include <cuda_runtime.h>
#include <cuda_bf16.h>
#include <cuda_fp16.h>
#include <cstdint>

#define NN      20000
#define EE      320000
#define IN_DIM  256
#define H0      4
#define D0      128
#define F1      512     // H0*D0
#define OUTF    64

// ---------------- device scratch (allocation-free contract) ----------------
__device__ __half g_feat1h[(size_t)NN * F1];   // layer-1 proj, fp16 (only consumer: agg1)
__device__ float g_feat2[(size_t)NN * OUTF];
__device__ __nv_bfloat16 g_xhi[(size_t)NN * IN_DIM];
__device__ __nv_bfloat16 g_xlo[(size_t)NN * IN_DIM];
__device__ __nv_bfloat16 g_hhi[(size_t)NN * F1];
__device__ __nv_bfloat16 g_hlo[(size_t)NN * F1];
__device__ __nv_bfloat16 g_w1t_hi[(size_t)F1 * IN_DIM];
__device__ __nv_bfloat16 g_w1t_lo[(size_t)F1 * IN_DIM];
__device__ __nv_bfloat16 g_w2t_hi[(size_t)OUTF * F1];
__device__ __nv_bfloat16 g_w2t_lo[(size_t)OUTF * F1];
__device__ float g_el1[NN * H0];
__device__ float g_er1[NN * H0];
__device__ float g_el2[NN];
__device__ float g_er2[NN];
__device__ int   g_deg[NN];
__device__ int   g_rowptr[NN + 1];
__device__ int   g_csr_src[EE];

// ---------------- helpers ----------------
__device__ __forceinline__ uint32_t smem_u32(const void* p) {
    uint32_t a;
    asm("{ .reg .u64 t; cvta.to.shared.u64 t, %1; cvt.u32.u64 %0, t; }" : "=r"(a) : "l"(p));
    return a;
}
__device__ __forceinline__ void ldsm_x4(uint32_t* r, uint32_t addr) {
    asm volatile("ldmatrix.sync.aligned.m8n8.x4.shared.b16 {%0,%1,%2,%3}, [%4];"
                 : "=r"(r[0]), "=r"(r[1]), "=r"(r[2]), "=r"(r[3]) : "r"(addr));
}
__device__ __forceinline__ void mma_bf16(float* c, const uint32_t* a, const uint32_t* b) {
    asm volatile(
        "mma.sync.aligned.m16n8k16.row.col.f32.bf16.bf16.f32 "
        "{%0,%1,%2,%3}, {%4,%5,%6,%7}, {%8,%9}, {%0,%1,%2,%3};"
        : "+f"(c[0]), "+f"(c[1]), "+f"(c[2]), "+f"(c[3])
        : "r"(a[0]), "r"(a[1]), "r"(a[2]), "r"(a[3]), "r"(b[0]), "r"(b[1]));
}
__device__ __forceinline__ uint32_t swz(int off) { return off ^ ((off >> 3) & 0x70); }
__device__ __forceinline__ float leaky(float e) { return fmaxf(e, 0.2f * e); }

// ---------------- CSR build ----------------
__global__ void zero_deg_kernel() {
    int i = blockIdx.x * blockDim.x + threadIdx.x;
    if (i < NN) g_deg[i] = 0;
}
__global__ void count_deg_kernel(const int* __restrict__ dst) {
    int i = blockIdx.x * blockDim.x + threadIdx.x;
    if (i < EE) atomicAdd(&g_deg[dst[i]], 1);
}
__global__ void scan_kernel() {
    __shared__ int partial[1024];
    const int CH = (NN + 1023) / 1024;
    int t = threadIdx.x;
    int base = t * CH;
    int s = 0;
    for (int i = 0; i < CH; i++) { int idx = base + i; if (idx < NN) s += g_deg[idx]; }
    partial[t] = s;
    __syncthreads();
    for (int off = 1; off < 1024; off <<= 1) {
        int v = (t >= off) ? partial[t - off] : 0;
        __syncthreads();
        partial[t] += v;
        __syncthreads();
    }
    int run = (t > 0) ? partial[t - 1] : 0;
    for (int i = 0; i < CH; i++) {
        int idx = base + i;
        if (idx < NN) { int d = g_deg[idx]; g_rowptr[idx] = run; run += d; g_deg[idx] = 0; }
    }
    if (t == 1023) g_rowptr[NN] = partial[1023];
}
__global__ void scatter_kernel(const int* __restrict__ src, const int* __restrict__ dst) {
    int i = blockIdx.x * blockDim.x + threadIdx.x;
    if (i >= EE) return;
    int d = dst[i];
    int pos = g_rowptr[d] + atomicAdd(&g_deg[d], 1);
    g_csr_src[pos] = src[i];
}

// ---------------- fused conversions + el/er zero ----------------
#define SPLIT_BLOCKS ((NN * IN_DIM / 4 + 255) / 256)
#define T1_BLOCKS    ((IN_DIM * F1 + 255) / 256)
#define T2_BLOCKS    ((F1 * OUTF + 255) / 256)
#define ZEL_COUNT    (NN * H0 * 2 + NN * 2)
#define ZEL_BLOCKS   ((ZEL_COUNT + 255) / 256)

__global__ void prep_kernel(const float* __restrict__ x, const float* __restrict__ W1,
                            const float* __restrict__ W2) {
    int b = blockIdx.x;
    int t = threadIdx.x;
    if (b < SPLIT_BLOCKS) {
        int i4 = (b * 256 + t) * 4;
        if (i4 >= NN * IN_DIM) return;
        float4 v = *(const float4*)(x + i4);
        __nv_bfloat16 h0 = __float2bfloat16(v.x), h1 = __float2bfloat16(v.y);
        __nv_bfloat16 h2 = __float2bfloat16(v.z), h3 = __float2bfloat16(v.w);
        __nv_bfloat16 l0 = __float2bfloat16(v.x - __bfloat162float(h0));
        __nv_bfloat16 l1 = __float2bfloat16(v.y - __bfloat162float(h1));
        __nv_bfloat16 l2 = __float2bfloat16(v.z - __bfloat162float(h2));
        __nv_bfloat16 l3 = __float2bfloat16(v.w - __bfloat162float(h3));
        __nv_bfloat162* ph = (__nv_bfloat162*)(g_xhi + i4);
        __nv_bfloat162* pl = (__nv_bfloat162*)(g_xlo + i4);
        ph[0] = __halves2bfloat162(h0, h1); ph[1] = __halves2bfloat162(h2, h3);
        pl[0] = __halves2bfloat162(l0, l1); pl[1] = __halves2bfloat162(l2, l3);
    } else if (b < SPLIT_BLOCKS + T1_BLOCKS) {
        int i = (b - SPLIT_BLOCKS) * 256 + t;
        if (i >= IN_DIM * F1) return;
        int k = i / F1, n = i - k * F1;
        float v = W1[i];
        __nv_bfloat16 h = __float2bfloat16(v);
        g_w1t_hi[(size_t)n * IN_DIM + k] = h;
        g_w1t_lo[(size_t)n * IN_DIM + k] = __float2bfloat16(v - __bfloat162float(h));
    } else if (b < SPLIT_BLOCKS + T1_BLOCKS + T2_BLOCKS) {
        int i = (b - SPLIT_BLOCKS - T1_BLOCKS) * 256 + t;
        if (i >= F1 * OUTF) return;
        int k = i / OUTF, n = i - k * OUTF;
        float v = W2[i];
        __nv_bfloat16 h = __float2bfloat16(v);
        g_w2t_hi[(size_t)n * F1 + k] = h;
        g_w2t_lo[(size_t)n * F1 + k] = __float2bfloat16(v - __bfloat162float(h));
    } else {
        int i = (b - SPLIT_BLOCKS - T1_BLOCKS - T2_BLOCKS) * 256 + t;
        if (i >= ZEL_COUNT) return;
        if (i < NN * H0) g_el1[i] = 0.f;
        else if (i < NN * H0 * 2) g_er1[i - NN * H0] = 0.f;
        else if (i < NN * H0 * 2 + NN) g_el2[i - NN * H0 * 2] = 0.f;
        else g_er2[i - NN * H0 * 2 - NN] = 0.f;
    }
}

// ---------------- bf16 mma.sync GEMM (256thr, 2 CTA/SM, warp 32x32) + fused el/er ----------------
__device__ __forceinline__ void load_tile64_async(uint32_t sb, int smem_off,
    const __nv_bfloat16* __restrict__ g, int ldK, int kc,
    int row0, int rows, int rlim, int tid) {
    int units = rows * 8;
    for (int i = tid; i < units; i += 256) {
        int r = i >> 3, seg = i & 7;
        int gr = row0 + r;
        int ok = (gr < rlim);
        int sz = ok ? 16 : 0;
        const void* src = g + (size_t)(ok ? gr : 0) * ldK + kc + seg * 8;
        int off = r * 128 + seg * 16;
        off ^= (off >> 3) & 0x70;
        asm volatile("cp.async.cg.shared.global [%0], [%1], 16, %2;"
                     :: "r"(sb + smem_off + off), "l"(src), "r"(sz));
    }
}

// BM=128, BN=64, 2 stages (48KB) -> ~97KB/CTA -> 2 CTA/SM.
// 8 warps: 4(m) x 2(n); warp tile 32x32; MT=2, NT=4.
// k-invariant swizzled bases; per-step offset applied via XOR:
// pre-swizzle base has bits[5:6]==0 and kkb in {0,32,64,96} never carries,
// so swz(base+kkb) == swz(base) ^ kkb  (XOR, NOT add).
template <int NSTAGE, int NH, int HEAD_DIV, bool FP16C>
__global__ void __launch_bounds__(256, 2) gemm_mma(
    const __nv_bfloat16* __restrict__ Ahi, const __nv_bfloat16* __restrict__ Alo,
    const __nv_bfloat16* __restrict__ Bhi, const __nv_bfloat16* __restrict__ Blo,
    void* __restrict__ Cv,
    const float* __restrict__ alv, const float* __restrict__ arv,
    float* __restrict__ el, float* __restrict__ er,
    int M, int Nc, int K) {
    extern __shared__ char smem[];
    constexpr int BN = 64;
    constexpr int OFF_AH = 0;
    constexpr int OFF_AL = 16384;
    constexpr int OFF_BH = 32768;
    constexpr int OFF_BL = OFF_BH + BN * 128;   // delta 8192
    constexpr int STAGE  = OFF_BL + BN * 128;
    constexpr int WN = 32;
    constexpr int NT = 4;
    constexpr int HEAD_COLS = BN * HEAD_DIV;

    const int tid = threadIdx.x;
    const int wid = tid >> 5;
    const int lane = tid & 31;
    const int wm = wid >> 1;
    const int wn = wid & 1;
    const int row0 = blockIdx.y * 128;
    const int col0 = blockIdx.x * BN;
    const int head = blockIdx.x / HEAD_DIV;
    const int hcol0 = col0 - head * HEAD_COLS;

    const uint32_t sb = smem_u32(smem);
    float* s_el = (float*)(smem + NSTAGE * STAGE);
    float* s_er = s_el + 128;

    if (tid < 128) { s_el[tid] = 0.f; s_er[tid] = 0.f; }

    float acc[2][NT][4];
#pragma unroll
    for (int i = 0; i < 2; i++)
#pragma unroll
        for (int j = 0; j < NT; j++)
#pragma unroll
            for (int q = 0; q < 4; q++) acc[i][j][q] = 0.f;

    const int a_r  = (lane & 15);
    const int a_kb = (lane >> 4) * 16;
    const int b_n  = (lane & 7) + ((lane >> 4) << 3);
    const int b_kb = ((lane >> 3) & 1) * 16;

    // swizzled intra-tile base offsets (k-invariant)
    uint32_t a_off[2], b_off[2];
#pragma unroll
    for (int mt = 0; mt < 2; mt++)
        a_off[mt] = swz((wm * 32 + mt * 16 + a_r) * 128 + a_kb);
#pragma unroll
    for (int bt = 0; bt < 2; bt++)
        b_off[bt] = swz((wn * WN + bt * 16 + b_n) * 128 + b_kb);

    const int nchunks = K >> 6;

#pragma unroll
    for (int p = 0; p < NSTAGE - 1; p++) {
        if (p < nchunks) {
            uint32_t sp = sb + p * STAGE;
            int kc = p << 6;
            load_tile64_async(sp, OFF_AH, Ahi, K, kc, row0, 128, M, tid);
            load_tile64_async(sp, OFF_AL, Alo, K, kc, row0, 128, M, tid);
            load_tile64_async(sp, OFF_BH, Bhi, K, kc, col0, BN, Nc, tid);
            load_tile64_async(sp, OFF_BL, Blo, K, kc, col0, BN, Nc, tid);
            asm volatile("cp.async.commit_group;");
        }
    }

    for (int c = 0; c < nchunks; c++) {
        if (c >= nchunks - (NSTAGE - 1))
            asm volatile("cp.async.wait_group 0;");
        else
            asm volatile("cp.async.wait_group %0;" :: "n"(NSTAGE - 2));
        __syncthreads();

        if (c + NSTAGE - 1 < nchunks) {
            int cn = c + NSTAGE - 1;
            uint32_t sn = sb + (cn % NSTAGE) * STAGE;
            int kc = cn << 6;
            load_tile64_async(sn, OFF_AH, Ahi, K, kc, row0, 128, M, tid);
            load_tile64_async(sn, OFF_AL, Alo, K, kc, row0, 128, M, tid);
            load_tile64_async(sn, OFF_BH, Bhi, K, kc, col0, BN, Nc, tid);
            load_tile64_async(sn, OFF_BL, Blo, K, kc, col0, BN, Nc, tid);
            asm volatile("cp.async.commit_group;");
        }

        const uint32_t scA = sb + (c % NSTAGE) * STAGE + OFF_AH;
        const uint32_t scB = sb + (c % NSTAGE) * STAGE + OFF_BH;
#pragma unroll
        for (int kk = 0; kk < 64; kk += 16) {
            const uint32_t kkb = kk * 2;
            const uint32_t ax0 = a_off[0] ^ kkb;
            const uint32_t ax1 = a_off[1] ^ kkb;
            const uint32_t bx0 = b_off[0] ^ kkb;
            const uint32_t bx1 = b_off[1] ^ kkb;
            uint32_t ah[2][4], al4[2][4];
            ldsm_x4(ah[0],  scA + ax0);
            ldsm_x4(al4[0], scA + 16384 + ax0);
            ldsm_x4(ah[1],  scA + ax1);
            ldsm_x4(al4[1], scA + 16384 + ax1);
            uint32_t bh[NT][2], bl[NT][2];
            {
                uint32_t t4[4];
                ldsm_x4(t4, scB + bx0);
                bh[0][0] = t4[0]; bh[0][1] = t4[1];
                bh[1][0] = t4[2]; bh[1][1] = t4[3];
                ldsm_x4(t4, scB + 8192 + bx0);
                bl[0][0] = t4[0]; bl[0][1] = t4[1];
                bl[1][0] = t4[2]; bl[1][1] = t4[3];
                ldsm_x4(t4, scB + bx1);
                bh[2][0] = t4[0]; bh[2][1] = t4[1];
                bh[3][0] = t4[2]; bh[3][1] = t4[3];
                ldsm_x4(t4, scB + 8192 + bx1);
                bl[2][0] = t4[0]; bl[2][1] = t4[1];
                bl[3][0] = t4[2]; bl[3][1] = t4[3];
            }
#pragma unroll
            for (int mt = 0; mt < 2; mt++)
#pragma unroll
                for (int nt = 0; nt < NT; nt++) {
                    mma_bf16(acc[mt][nt], ah[mt], bh[nt]);
                    mma_bf16(acc[mt][nt], ah[mt], bl[nt]);
                    mma_bf16(acc[mt][nt], al4[mt], bh[nt]);
                }
        }
        __syncthreads();
    }

    float va[NT][2], vr[NT][2];
#pragma unroll
    for (int nt = 0; nt < NT; nt++) {
        int cL = hcol0 + wn * WN + nt * 8 + (lane & 3) * 2;
        va[nt][0] = alv[head * HEAD_COLS + cL];  va[nt][1] = alv[head * HEAD_COLS + cL + 1];
        vr[nt][0] = arv[head * HEAD_COLS + cL];  vr[nt][1] = arv[head * HEAD_COLS + cL + 1];
    }

#pragma unroll
    for (int mt = 0; mt < 2; mt++) {
        int rL0 = wm * 32 + mt * 16 + (lane >> 2);
        int m0 = row0 + rL0;
        float e0 = 0.f, r0 = 0.f, e1 = 0.f, r1 = 0.f;
#pragma unroll
        for (int nt = 0; nt < NT; nt++) {
            int n0 = col0 + wn * WN + nt * 8 + (lane & 3) * 2;
            if (FP16C) {
                __half* Ch = (__half*)Cv;
                if (m0 < M)
                    *(__half2*)(Ch + (size_t)m0 * Nc + n0) =
                        __floats2half2_rn(acc[mt][nt][0], acc[mt][nt][1]);
                if (m0 + 8 < M)
                    *(__half2*)(Ch + (size_t)(m0 + 8) * Nc + n0) =
                        __floats2half2_rn(acc[mt][nt][2], acc[mt][nt][3]);
            } else {
                float* Cf = (float*)Cv;
                if (m0 < M)
                    *(float2*)(Cf + (size_t)m0 * Nc + n0) = make_float2(acc[mt][nt][0], acc[mt][nt][1]);
                if (m0 + 8 < M)
                    *(float2*)(Cf + (size_t)(m0 + 8) * Nc + n0) = make_float2(acc[mt][nt][2], acc[mt][nt][3]);
            }
            e0 += acc[mt][nt][0] * va[nt][0] + acc[mt][nt][1] * va[nt][1];
            r0 += acc[mt][nt][0] * vr[nt][0] + acc[mt][nt][1] * vr[nt][1];
            e1 += acc[mt][nt][2] * va[nt][0] + acc[mt][nt][3] * va[nt][1];
            r1 += acc[mt][nt][2] * vr[nt][0] + acc[mt][nt][3] * vr[nt][1];
        }
#pragma unroll
        for (int o = 1; o <= 2; o <<= 1) {
            e0 += __shfl_xor_sync(0xffffffffu, e0, o);
            r0 += __shfl_xor_sync(0xffffffffu, r0, o);
            e1 += __shfl_xor_sync(0xffffffffu, e1, o);
            r1 += __shfl_xor_sync(0xffffffffu, r1, o);
        }
        if ((lane & 3) == 0) {
            atomicAdd(&s_el[rL0], e0);
            atomicAdd(&s_er[rL0], r0);
            atomicAdd(&s_el[rL0 + 8], e1);
            atomicAdd(&s_er[rL0 + 8], r1);
        }
    }
    __syncthreads();
    if (tid < 128) {
        int node = row0 + tid;
        if (node < M) {
            if (HEAD_DIV == 1) {
                el[node * NH + head] = s_el[tid];
                er[node * NH + head] = s_er[tid];
            } else {
                atomicAdd(&el[node * NH + head], s_el[tid]);
                atomicAdd(&er[node * NH + head], s_er[tid]);
            }
        }
    }
}

// ---------------- layer-1 aggregation (fp16 feat gather) ----------------
__device__ __forceinline__ void acc_h16_edge(float* acc, const __half* fbase, float a) {
    const uint4* fp = (const uint4*)fbase;
    uint4 u0 = fp[0];
    uint4 u1 = fp[1];
    const uint32_t w[8] = {u0.x, u0.y, u0.z, u0.w, u1.x, u1.y, u1.z, u1.w};
#pragma unroll
    for (int q = 0; q < 8; q++) {
        float2 v = __half22float2(*(const __half2*)&w[q]);
        acc[q * 2 + 0] += a * v.x;
        acc[q * 2 + 1] += a * v.y;
    }
}

__global__ void agg1_kernel(const float* __restrict__ b1) {
    int node = (blockIdx.x * blockDim.x + threadIdx.x) >> 5;
    int lane = threadIdx.x & 31;
    if (node >= NN) return;
    int beg = g_rowptr[node], end = g_rowptr[node + 1];

    int hh = lane & 3;
    float er_hh = g_er1[node * 4 + hh];

    float m = -INFINITY;
    for (int j = beg + (lane >> 2); j < end; j += 8) {
        int s = g_csr_src[j];
        m = fmaxf(m, leaky(g_el1[s * 4 + hh] + er_hh));
    }
#pragma unroll
    for (int o = 4; o < 32; o <<= 1) m = fmaxf(m, __shfl_xor_sync(0xffffffffu, m, o));

    float ssum = 0.f;
    for (int j = beg + (lane >> 2); j < end; j += 8) {
        int s = g_csr_src[j];
        ssum += __expf(leaky(g_el1[s * 4 + hh] + er_hh) - m);
    }
#pragma unroll
    for (int o = 4; o < 32; o <<= 1) ssum += __shfl_xor_sync(0xffffffffu, ssum, o);

    int myhead = lane >> 3;
    float m_h = __shfl_sync(0xffffffffu, m, myhead);
    float s_h = __shfl_sync(0xffffffffu, ssum, myhead);
    float er_mh = g_er1[node * 4 + myhead];
    float inv_s = 1.f / s_h;

    float acc[16];
#pragma unroll
    for (int q = 0; q < 16; q++) acc[q] = 0.f;

    int j = beg;
    for (; j + 4 <= end; j += 4) {
        int s0 = g_csr_src[j];
        int s1 = g_csr_src[j + 1];
        int s2 = g_csr_src[j + 2];
        int s3 = g_csr_src[j + 3];
        float a0 = __expf(leaky(g_el1[s0 * 4 + myhead] + er_mh) - m_h) * inv_s;
        float a1 = __expf(leaky(g_el1[s1 * 4 + myhead] + er_mh) - m_h) * inv_s;
        float a2 = __expf(leaky(g_el1[s2 * 4 + myhead] + er_mh) - m_h) * inv_s;
        float a3 = __expf(leaky(g_el1[s3 * 4 + myhead] + er_mh) - m_h) * inv_s;
        acc_h16_edge(acc, g_feat1h + (size_t)s0 * F1 + lane * 16, a0);
        acc_h16_edge(acc, g_feat1h + (size_t)s1 * F1 + lane * 16, a1);
        acc_h16_edge(acc, g_feat1h + (size_t)s2 * F1 + lane * 16, a2);
        acc_h16_edge(acc, g_feat1h + (size_t)s3 * F1 + lane * 16, a3);
    }
    for (; j < end; j++) {
        int s0 = g_csr_src[j];
        float a0 = __expf(leaky(g_el1[s0 * 4 + myhead] + er_mh) - m_h) * inv_s;
        acc_h16_edge(acc, g_feat1h + (size_t)s0 * F1 + lane * 16, a0);
    }

    size_t obase = (size_t)node * F1 + lane * 16;
#pragma unroll
    for (int q = 0; q < 4; q++) {
        float vv[4];
#pragma unroll
        for (int u = 0; u < 4; u++) {
            float v = acc[q * 4 + u] + b1[lane * 16 + q * 4 + u];
            vv[u] = v > 0.f ? v : expm1f(v);
        }
        __nv_bfloat16 h0 = __float2bfloat16(vv[0]), h1 = __float2bfloat16(vv[1]);
        __nv_bfloat16 h2 = __float2bfloat16(vv[2]), h3 = __float2bfloat16(vv[3]);
        __nv_bfloat16 l0 = __float2bfloat16(vv[0] - __bfloat162float(h0));
        __nv_bfloat16 l1 = __float2bfloat16(vv[1] - __bfloat162float(h1));
        __nv_bfloat16 l2 = __float2bfloat16(vv[2] - __bfloat162float(h2));
        __nv_bfloat16 l3 = __float2bfloat16(vv[3] - __bfloat162float(h3));
        __nv_bfloat162* ph = (__nv_bfloat162*)(g_hhi + obase + q * 4);
        __nv_bfloat162* pl = (__nv_bfloat162*)(g_hlo + obase + q * 4);
        ph[0] = __halves2bfloat162(h0, h1); ph[1] = __halves2bfloat162(h2, h3);
        pl[0] = __halves2bfloat162(l0, l1); pl[1] = __halves2bfloat162(l2, l3);
    }
}

// ---------------- layer-2 aggregation ----------------
__global__ void agg2_kernel(const float* __restrict__ b2, float* __restrict__ out) {
    int node = (blockIdx.x * blockDim.x + threadIdx.x) >> 5;
    int lane = threadIdx.x & 31;
    if (node >= NN) return;
    int beg = g_rowptr[node], end = g_rowptr[node + 1];

    float er_n = g_er2[node];

    float m = -INFINITY;
    for (int j = beg + lane; j < end; j += 32)
        m = fmaxf(m, leaky(g_el2[g_csr_src[j]] + er_n));
#pragma unroll
    for (int o = 16; o > 0; o >>= 1) m = fmaxf(m, __shfl_xor_sync(0xffffffffu, m, o));

    float ssum = 0.f;
    for (int j = beg + lane; j < end; j += 32)
        ssum += __expf(leaky(g_el2[g_csr_src[j]] + er_n) - m);
#pragma unroll
    for (int o = 16; o > 0; o >>= 1) ssum += __shfl_xor_sync(0xffffffffu, ssum, o);
    float inv_s = 1.f / ssum;

    float acc0 = 0.f, acc1 = 0.f;
    int j = beg;
    for (; j + 4 <= end; j += 4) {
        int s0 = g_csr_src[j];
        int s1 = g_csr_src[j + 1];
        int s2 = g_csr_src[j + 2];
        int s3 = g_csr_src[j + 3];
        float a0 = __expf(leaky(g_el2[s0] + er_n) - m) * inv_s;
        float a1 = __expf(leaky(g_el2[s1] + er_n) - m) * inv_s;
        float a2 = __expf(leaky(g_el2[s2] + er_n) - m) * inv_s;
        float a3 = __expf(leaky(g_el2[s3] + er_n) - m) * inv_s;
        float2 v0 = *(const float2*)(g_feat2 + (size_t)s0 * OUTF + lane * 2);
        float2 v1 = *(const float2*)(g_feat2 + (size_t)s1 * OUTF + lane * 2);
        float2 v2 = *(const float2*)(g_feat2 + (size_t)s2 * OUTF + lane * 2);
        float2 v3 = *(const float2*)(g_feat2 + (size_t)s3 * OUTF + lane * 2);
        acc0 += a0 * v0.x + a1 * v1.x + a2 * v2.x + a3 * v3.x;
        acc1 += a0 * v0.y + a1 * v1.y + a2 * v2.y + a3 * v3.y;
    }
    for (; j < end; j++) {
        int s0 = g_csr_src[j];
        float a0 = __expf(leaky(g_el2[s0] + er_n) - m) * inv_s;
        float2 v0 = *(const float2*)(g_feat2 + (size_t)s0 * OUTF + lane * 2);
        acc0 += a0 * v0.x;
        acc1 += a0 * v0.y;
    }
    float2 o2;
    o2.x = acc0 + b2[lane * 2 + 0];
    o2.y = acc1 + b2[lane * 2 + 1];
    *(float2*)(out + (size_t)node * OUTF + lane * 2) = o2;
}

// ---------------- host launch ----------------
extern "C" void kernel_launch(void* const* d_in, const int* in_sizes, int n_in,
                              void* d_out, int out_size) {
    const float* x   = (const float*)d_in[0];
    const int*   src = (const int*)d_in[1];
    const int*   dst = (const int*)d_in[2];
    const float* W1  = (const float*)d_in[3];
    const float* al1 = (const float*)d_in[4];
    const float* ar1 = (const float*)d_in[5];
    const float* b1  = (const float*)d_in[6];
    const float* W2  = (const float*)d_in[7];
    const float* al2 = (const float*)d_in[8];
    const float* ar2 = (const float*)d_in[9];
    const float* b2  = (const float*)d_in[10];
    float* out = (float*)d_out;

    void *p_feat1h, *p_feat2, *p_el1, *p_er1, *p_el2, *p_er2;
    void *p_xhi, *p_xlo, *p_hhi, *p_hlo, *p_w1h, *p_w1l, *p_w2h, *p_w2l;
    cudaGetSymbolAddress(&p_feat1h, g_feat1h);
    cudaGetSymbolAddress(&p_feat2, g_feat2);
    cudaGetSymbolAddress(&p_el1, g_el1);
    cudaGetSymbolAddress(&p_er1, g_er1);
    cudaGetSymbolAddress(&p_el2, g_el2);
    cudaGetSymbolAddress(&p_er2, g_er2);
    cudaGetSymbolAddress(&p_xhi, g_xhi);
    cudaGetSymbolAddress(&p_xlo, g_xlo);
    cudaGetSymbolAddress(&p_hhi, g_hhi);
    cudaGetSymbolAddress(&p_hlo, g_hlo);
    cudaGetSymbolAddress(&p_w1h, g_w1t_hi);
    cudaGetSymbolAddress(&p_w1l, g_w1t_lo);
    cudaGetSymbolAddress(&p_w2h, g_w2t_hi);
    cudaGetSymbolAddress(&p_w2l, g_w2t_lo);

    const int SMEM = 2 * 49152 + 1024;
    static bool attrs_set = false;
    if (!attrs_set) {
        cudaFuncSetAttribute((const void*)gemm_mma<2, H0, 2, true>,
                             cudaFuncAttributeMaxDynamicSharedMemorySize, SMEM);
        cudaFuncSetAttribute((const void*)gemm_mma<2, 1, 1, false>,
                             cudaFuncAttributeMaxDynamicSharedMemorySize, SMEM);
        attrs_set = true;
    }

    static cudaStream_t s2 = nullptr;
    static cudaEvent_t evFork = nullptr, evJoin = nullptr;
    if (!s2) {
        cudaStreamCreateWithFlags(&s2, cudaStreamNonBlocking);
        cudaEventCreateWithFlags(&evFork, cudaEventDisableTiming);
        cudaEventCreateWithFlags(&evJoin, cudaEventDisableTiming);
    }

    cudaEventRecord(evFork, 0);
    cudaStreamWaitEvent(s2, evFork, 0);

    zero_deg_kernel<<<(NN + 255) / 256, 256, 0, s2>>>();                   // #0
    count_deg_kernel<<<(EE + 255) / 256, 256, 0, s2>>>(dst);               // #1

    prep_kernel<<<SPLIT_BLOCKS + T1_BLOCKS + T2_BLOCKS + ZEL_BLOCKS, 256>>>(x, W1, W2); // #2
    {
        dim3 grid(F1 / 64, (NN + 127) / 128);
        gemm_mma<2, H0, 2, true><<<grid, 256, SMEM>>>((const __nv_bfloat16*)p_xhi,  // #3
                                                      (const __nv_bfloat16*)p_xlo,
                                                      (const __nv_bfloat16*)p_w1h,
                                                      (const __nv_bfloat16*)p_w1l,
                                                      p_feat1h, al1, ar1,
                                                      (float*)p_el1, (float*)p_er1,
                                                      NN, F1, IN_DIM);
    }

    scan_kernel<<<1, 1024, 0, s2>>>();                                     // #4
    scatter_kernel<<<(EE + 255) / 256, 256, 0, s2>>>(src, dst);            // #5
    cudaEventRecord(evJoin, s2);

    cudaStreamWaitEvent(0, evJoin, 0);
    agg1_kernel<<<(NN * 32 + 255) / 256, 256>>>(b1);                       // #6

    {
        dim3 grid(1, (NN + 127) / 128);
        gemm_mma<2, 1, 1, false><<<grid, 256, SMEM>>>((const __nv_bfloat16*)p_hhi,  // #7
                                                      (const __nv_bfloat16*)p_hlo,
                                                      (const __nv_bfloat16*)p_w2h,
                                                      (const __nv_bfloat16*)p_w2l,
                                                      p_feat2, al2, ar2,
                                                      (float*)p_el2, (float*)p_er2,
                                                      NN, OUTF, F1);
    }
    agg2_kernel<<<(NN * 32 + 255) / 256, 256>>>(b2, out);                  // #8
}